// round 2
// baseline (speedup 1.0000x reference)
#include <cuda_runtime.h>
#include <math.h>
#include <cuda_bf16.h>

#define N_OBJ  4096
#define H      512
#define IN_DIM 1024
#define G6     3072   // 6*H (forward gates)
#define G5     2560   // 5*H (backward gates)
#define NLEV   13
#define BM 128
#define BN 128
#define BK 16

// ---------------- scratch (no allocation allowed -> device globals) ----------
__device__ float g_px_fw[N_OBJ * H];
__device__ float g_x2_fw[N_OBJ * G6];
__device__ float g_px_bw[N_OBJ * H];
__device__ float g_x2_bw[N_OBJ * G5];
__device__ float g_h_fw[(N_OBJ + 1) * H];   // slot N_OBJ = permanent zeros
__device__ float g_c_fw[(N_OBJ + 1) * H];
__device__ float g_h_bw[(N_OBJ + 1) * H];
__device__ float g_c_bw[(N_OBJ + 1) * H];
__device__ float g_G[2048 * G6];            // per-level gate preactivations
__device__ float g_feat[N_OBJ * IN_DIM];    // layer-1 input

__device__ __forceinline__ float sigm(float x) { return 1.0f / (1.0f + expf(-x)); }

__global__ void zero_slots_kernel() {
    int t = threadIdx.x;
    g_h_fw[N_OBJ * H + t] = 0.f;
    g_c_fw[N_OBJ * H + t] = 0.f;
    g_h_bw[N_OBJ * H + t] = 0.f;
    g_c_bw[N_OBJ * H + t] = 0.f;
}

// =============================================================================
// Unified 128x128 SGEMM, double-buffered, 8x8 per thread.
//   C = A · B^T (+ bias1 [+ bias2] [+ x2 row-gathered])
// MODE 0: A plain [M,K] (projections).           B = B1 [N,K].
// MODE 1: A row r = h[idx1[node]] | h[idx2[node]] (K halves), node=ls+r.
//         B row n = B1[n] | B2[n]  (Wl | Wr, each [N,512]).  K must be 1024.
// MODE 2: A row r = h[idx1[node]] (parent).      B = B1 [N,512]. K=512.
// =============================================================================
template<int MODE>
__global__ void __launch_bounds__(256, 2)
gemm128(const float* __restrict__ Abase,
        const float* __restrict__ B1, const float* __restrict__ B2,
        const float* __restrict__ bias1, const float* __restrict__ bias2,
        const float* __restrict__ x2,
        float* __restrict__ C,
        const int* __restrict__ idx1, const int* __restrict__ idx2,
        int N, int K, int levelStart, int m)
{
    __shared__ float As[2][BK][BM + 4];
    __shared__ float Bs[2][BK][BN + 4];

    const int tid = threadIdx.x;
    const int tx = tid & 15, ty = tid >> 4;
    const int rowBase = blockIdx.y * BM;
    const int colBase = blockIdx.x * BN;
    const int lr = tid >> 2;           // 0..63 loader row
    const int lk = (tid & 3) << 2;     // 0,4,8,12 loader k offset

    // ---- per-loader-row A source pointers -----------------------------------
    const float *pa0a, *pa1a, *pa0b, *pa1b;
    if (MODE == 0) {
        pa0a = Abase + (size_t)(rowBase + lr) * K + lk;
        pa1a = Abase + (size_t)(rowBase + lr + 64) * K + lk;
        pa0b = pa0a; pa1b = pa1a;
    } else {
        int r0 = rowBase + lr;       if (r0 >= m) r0 = m - 1;
        int r1 = rowBase + lr + 64;  if (r1 >= m) r1 = m - 1;
        const int n0 = levelStart + r0, n1 = levelStart + r1;
        pa0a = Abase + (size_t)idx1[n0] * H + lk;
        pa1a = Abase + (size_t)idx1[n1] * H + lk;
        if (MODE == 1) {
            pa0b = Abase + (size_t)idx2[n0] * H + lk;
            pa1b = Abase + (size_t)idx2[n1] * H + lk;
        } else { pa0b = pa0a; pa1b = pa1a; }
    }
    // ---- per-loader-row B source pointers -----------------------------------
    const int kb = (MODE == 1) ? 512 : K;     // B row stride
    const float* pb0a = B1 + (size_t)(colBase + lr) * kb + lk;
    const float* pb1a = B1 + (size_t)(colBase + lr + 64) * kb + lk;
    const float* pb0b = (MODE == 1) ? (B2 + (size_t)(colBase + lr) * kb + lk) : pb0a;
    const float* pb1b = (MODE == 1) ? (B2 + (size_t)(colBase + lr + 64) * kb + lk) : pb1a;

    float acc[8][8];
#pragma unroll
    for (int i = 0; i < 8; i++)
#pragma unroll
        for (int j = 0; j < 8; j++) acc[i][j] = 0.f;

    float4 ra0, ra1, rb0, rb1;

    auto gload = [&](int k0) {
        if (MODE == 1 && k0 >= 512) {
            int ko = k0 - 512;
            ra0 = *(const float4*)(pa0b + ko);
            ra1 = *(const float4*)(pa1b + ko);
            rb0 = *(const float4*)(pb0b + ko);
            rb1 = *(const float4*)(pb1b + ko);
        } else {
            ra0 = *(const float4*)(pa0a + k0);
            ra1 = *(const float4*)(pa1a + k0);
            rb0 = *(const float4*)(pb0a + k0);
            rb1 = *(const float4*)(pb1a + k0);
        }
    };
    auto sstore = [&](int b) {
        As[b][lk + 0][lr] = ra0.x; As[b][lk + 1][lr] = ra0.y;
        As[b][lk + 2][lr] = ra0.z; As[b][lk + 3][lr] = ra0.w;
        As[b][lk + 0][lr + 64] = ra1.x; As[b][lk + 1][lr + 64] = ra1.y;
        As[b][lk + 2][lr + 64] = ra1.z; As[b][lk + 3][lr + 64] = ra1.w;
        Bs[b][lk + 0][lr] = rb0.x; Bs[b][lk + 1][lr] = rb0.y;
        Bs[b][lk + 2][lr] = rb0.z; Bs[b][lk + 3][lr] = rb0.w;
        Bs[b][lk + 0][lr + 64] = rb1.x; Bs[b][lk + 1][lr + 64] = rb1.y;
        Bs[b][lk + 2][lr + 64] = rb1.z; Bs[b][lk + 3][lr + 64] = rb1.w;
    };

    const int nTiles = K / BK;
    gload(0);
    sstore(0);
    __syncthreads();

    for (int t = 0; t < nTiles; t++) {
        const int cur = t & 1;
        if (t + 1 < nTiles) gload((t + 1) * BK);
        // compute on buffer `cur`
#pragma unroll
        for (int kk = 0; kk < BK; kk++) {
            float4 a0 = *(const float4*)&As[cur][kk][ty * 8];
            float4 a1 = *(const float4*)&As[cur][kk][ty * 8 + 4];
            float4 b0 = *(const float4*)&Bs[cur][kk][tx * 8];
            float4 b1 = *(const float4*)&Bs[cur][kk][tx * 8 + 4];
            float av[8] = {a0.x, a0.y, a0.z, a0.w, a1.x, a1.y, a1.z, a1.w};
            float bv[8] = {b0.x, b0.y, b0.z, b0.w, b1.x, b1.y, b1.z, b1.w};
#pragma unroll
            for (int i = 0; i < 8; i++)
#pragma unroll
                for (int j = 0; j < 8; j++)
                    acc[i][j] += av[i] * bv[j];
        }
        if (t + 1 < nTiles) {
            sstore((t + 1) & 1);
            __syncthreads();
        }
    }

    // ---- epilogue -------------------------------------------------------------
    const int colT = colBase + tx * 8;
    float bv[8];
#pragma unroll
    for (int j = 0; j < 8; j++) {
        bv[j] = bias1[colT + j];
        if (MODE == 1) bv[j] += bias2[colT + j];
    }
#pragma unroll
    for (int i = 0; i < 8; i++) {
        const int row = rowBase + ty * 8 + i;
        if (MODE == 0 || row < m) {
            float v[8];
#pragma unroll
            for (int j = 0; j < 8; j++) v[j] = acc[i][j] + bv[j];
            if (MODE != 0) {
                const float* xr = x2 + (size_t)(levelStart + row) * N + colT;
#pragma unroll
                for (int j = 0; j < 8; j++) v[j] += xr[j];
            }
            float* cr = C + (size_t)row * N + colT;
            *(float4*)(cr)     = make_float4(v[0], v[1], v[2], v[3]);
            *(float4*)(cr + 4) = make_float4(v[4], v[5], v[6], v[7]);
        }
    }
}

// --------- forward gates: c,h update for one level ---------------------------
__global__ void gates_fw(const float* __restrict__ G, const float* __restrict__ px,
                         float* __restrict__ cbuf, float* __restrict__ hbuf,
                         const int* __restrict__ lch, const int* __restrict__ rch,
                         int levelStart) {
    const int j = blockIdx.x;
    const int col = threadIdx.x;
    const int node = levelStart + j;
    const float* g = G + (size_t)j * G6;
    float iv = sigm(g[col]);
    float ov = sigm(g[H + col]);
    float fl = sigm(g[2 * H + col]);
    float fr = sigm(g[3 * H + col]);
    float uv = tanhf(g[4 * H + col]);
    float rv = sigm(g[5 * H + col]);
    float cl = cbuf[(size_t)lch[node] * H + col];
    float cr = cbuf[(size_t)rch[node] * H + col];
    float c = iv * uv + fl * cl + fr * cr;
    float hc = ov * tanhf(c);
    float hf = rv * hc + (1.f - rv) * px[(size_t)node * H + col];
    cbuf[(size_t)node * H + col] = c;
    hbuf[(size_t)node * H + col] = hf;
}

// --------- backward gates -----------------------------------------------------
__global__ void gates_bw(const float* __restrict__ G, const float* __restrict__ px,
                         float* __restrict__ cbuf, float* __restrict__ hbuf,
                         const int* __restrict__ par, int levelStart) {
    const int j = blockIdx.x;
    const int col = threadIdx.x;
    const int node = levelStart + j;
    const float* g = G + (size_t)j * G5;
    float iv = sigm(g[col]);
    float ov = sigm(g[H + col]);
    float fv = sigm(g[2 * H + col]);
    float uv = tanhf(g[3 * H + col]);
    float rv = sigm(g[4 * H + col]);
    float cp = cbuf[(size_t)par[node] * H + col];
    float c = iv * uv + fv * cp;
    float hc = ov * tanhf(c);
    float hf = rv * hc + (1.f - rv) * px[(size_t)node * H + col];
    cbuf[(size_t)node * H + col] = c;
    hbuf[(size_t)node * H + col] = hf;
}

// --------- concat [h_fw | h_bw] -> dest [N_OBJ, 1024] --------------------------
__global__ void concat_k(const float* __restrict__ hf, const float* __restrict__ hb,
                         float* __restrict__ dst) {
    int t = blockIdx.x * blockDim.x + threadIdx.x;
    if (t < N_OBJ * H) {
        int row = t / H, col = t % H;
        dst[(size_t)row * IN_DIM + col]     = hf[t];
        dst[(size_t)row * IN_DIM + H + col] = hb[t];
    }
}

// ------------------------------- launch ---------------------------------------
extern "C" void kernel_launch(void* const* d_in, const int* in_sizes, int n_in,
                              void* d_out, int out_size) {
    const float* features = (const float*)d_in[0];
    const float* fw_Wp = (const float*)d_in[1];
    const float* fw_bp = (const float*)d_in[2];
    const float* fw_Wx = (const float*)d_in[3];
    const float* fw_bx = (const float*)d_in[4];
    const float* fw_Wl = (const float*)d_in[5];
    const float* fw_bl = (const float*)d_in[6];
    const float* fw_Wr = (const float*)d_in[7];
    const float* fw_br = (const float*)d_in[8];
    const float* bw_Wp = (const float*)d_in[9];
    const float* bw_bp = (const float*)d_in[10];
    const float* bw_Wx = (const float*)d_in[11];
    const float* bw_bx = (const float*)d_in[12];
    const float* bw_Wh = (const float*)d_in[13];
    const float* bw_bh = (const float*)d_in[14];
    const int* left   = (const int*)d_in[17];
    const int* right  = (const int*)d_in[18];
    const int* parent = (const int*)d_in[19];
    float* out = (float*)d_out;

    float *px_fw, *x2_fw, *px_bw, *x2_bw, *h_fw, *c_fw, *h_bw, *c_bw, *Gs, *feat;
    cudaGetSymbolAddress((void**)&px_fw, g_px_fw);
    cudaGetSymbolAddress((void**)&x2_fw, g_x2_fw);
    cudaGetSymbolAddress((void**)&px_bw, g_px_bw);
    cudaGetSymbolAddress((void**)&x2_bw, g_x2_bw);
    cudaGetSymbolAddress((void**)&h_fw, g_h_fw);
    cudaGetSymbolAddress((void**)&c_fw, g_c_fw);
    cudaGetSymbolAddress((void**)&h_bw, g_h_bw);
    cudaGetSymbolAddress((void**)&c_bw, g_c_bw);
    cudaGetSymbolAddress((void**)&Gs, g_G);
    cudaGetSymbolAddress((void**)&feat, g_feat);

    zero_slots_kernel<<<1, H>>>();

    static const int LSTART[NLEV] = {0, 1, 3, 7, 15, 31, 63, 127, 255, 511, 1023, 2047, 4095};
    static const int LSIZE[NLEV]  = {1, 2, 4, 8, 16, 32, 64, 128, 256, 512, 1024, 2048, 1};

    const float* cur = features;

    for (int l = 0; l < 2; l++) {
        const float* Wp_f = fw_Wp + (size_t)l * H * IN_DIM;
        const float* bp_f = fw_bp + (size_t)l * H;
        const float* Wx_f = fw_Wx + (size_t)l * G6 * IN_DIM;
        const float* bx_f = fw_bx + (size_t)l * G6;
        const float* Wl_  = fw_Wl + (size_t)l * G6 * H;
        const float* bl_  = fw_bl + (size_t)l * G6;
        const float* Wr_  = fw_Wr + (size_t)l * G6 * H;
        const float* br_  = fw_br + (size_t)l * G6;
        const float* Wp_b = bw_Wp + (size_t)l * H * IN_DIM;
        const float* bp_b = bw_bp + (size_t)l * H;
        const float* Wx_b = bw_Wx + (size_t)l * G5 * IN_DIM;
        const float* bx_b = bw_bx + (size_t)l * G5;
        const float* Wh_  = bw_Wh + (size_t)l * G5 * H;
        const float* bh_  = bw_bh + (size_t)l * G5;

        // batched input projections (MODE 0)
        gemm128<0><<<dim3(H  / BN, N_OBJ / BM), 256>>>(cur, Wp_f, nullptr, bp_f, nullptr,
                                                       nullptr, px_fw, nullptr, nullptr,
                                                       H,  IN_DIM, 0, N_OBJ);
        gemm128<0><<<dim3(G6 / BN, N_OBJ / BM), 256>>>(cur, Wx_f, nullptr, bx_f, nullptr,
                                                       nullptr, x2_fw, nullptr, nullptr,
                                                       G6, IN_DIM, 0, N_OBJ);
        gemm128<0><<<dim3(H  / BN, N_OBJ / BM), 256>>>(cur, Wp_b, nullptr, bp_b, nullptr,
                                                       nullptr, px_bw, nullptr, nullptr,
                                                       H,  IN_DIM, 0, N_OBJ);
        gemm128<0><<<dim3(G5 / BN, N_OBJ / BM), 256>>>(cur, Wx_b, nullptr, bx_b, nullptr,
                                                       nullptr, x2_bw, nullptr, nullptr,
                                                       G5, IN_DIM, 0, N_OBJ);

        // forward: leaves -> root (deepest level first)
        for (int d = NLEV - 1; d >= 0; d--) {
            int m = LSIZE[d], s = LSTART[d];
            gemm128<1><<<dim3(G6 / BN, (m + BM - 1) / BM), 256>>>(
                h_fw, Wl_, Wr_, bl_, br_, x2_fw, Gs, left, right, G6, 1024, s, m);
            gates_fw<<<m, H>>>(Gs, px_fw, c_fw, h_fw, left, right, s);
        }
        // backward: root -> leaves
        for (int d = 0; d < NLEV; d++) {
            int m = LSIZE[d], s = LSTART[d];
            gemm128<2><<<dim3(G5 / BN, (m + BM - 1) / BM), 256>>>(
                h_bw, Wh_, nullptr, bh_, nullptr, x2_bw, Gs, parent, nullptr, G5, 512, s, m);
            gates_bw<<<m, H>>>(Gs, px_bw, c_bw, h_bw, parent, s);
        }

        float* dst = (l == 1) ? out : feat;
        concat_k<<<(N_OBJ * H + 255) / 256, 256>>>(h_fw, h_bw, dst);
        cur = feat;
    }
}

// round 3
// speedup vs baseline: 1.3147x; 1.3147x over previous
#include <cuda_runtime.h>
#include <math.h>

#define N_OBJ  4096
#define H      512
#define IN_DIM 1024
#define G6     3072
#define G5     2560
#define NLEV   13
#define BM 128
#define BN 128
#define BK 8
#define PITCH 132

// ---------------- scratch (no allocation allowed -> device globals) ----------
__device__ float g_px_fw[N_OBJ * H];
__device__ float g_x2_fw[N_OBJ * G6];
__device__ float g_px_bw[N_OBJ * H];
__device__ float g_x2_bw[N_OBJ * G5];
__device__ float g_h_fw[(N_OBJ + 1) * H];   // slot N_OBJ = permanent zeros
__device__ float g_c_fw[(N_OBJ + 1) * H];
__device__ float g_h_bw[(N_OBJ + 1) * H];
__device__ float g_c_bw[(N_OBJ + 1) * H];
__device__ float g_G[1024 * G6];            // fw gate preacts (max gemm level m=1024)
__device__ float g_Yp[2048 * G5];           // bw parent projections h[p]@Wh^T
__device__ float g_feat[N_OBJ * IN_DIM];

__device__ __forceinline__ float sigm(float x) { return 1.0f / (1.0f + expf(-x)); }

__global__ void zero_slots_kernel() {
    int t = threadIdx.x;
    g_h_fw[N_OBJ * H + t] = 0.f;
    g_c_fw[N_OBJ * H + t] = 0.f;
    g_h_bw[N_OBJ * H + t] = 0.f;
    g_c_bw[N_OBJ * H + t] = 0.f;
}

// ---- shared GEMM mainloop: 128x128x8, double buffered, 8x8 frag, 256 thr ----
// requires in scope: As,Bs,tid,tx,ty,lr,lk and a GLOAD(k0) macro filling ra,rb.
#define GEMM_MAIN(NT, GLOAD)                                                      \
    float acc[8][8];                                                              \
    _Pragma("unroll") for (int i = 0; i < 8; i++)                                 \
    _Pragma("unroll") for (int j = 0; j < 8; j++) acc[i][j] = 0.f;                \
    float4 ra, rb;                                                                \
    GLOAD(0);                                                                     \
    As[0][lk+0][lr]=ra.x; As[0][lk+1][lr]=ra.y; As[0][lk+2][lr]=ra.z; As[0][lk+3][lr]=ra.w; \
    Bs[0][lk+0][lr]=rb.x; Bs[0][lk+1][lr]=rb.y; Bs[0][lk+2][lr]=rb.z; Bs[0][lk+3][lr]=rb.w; \
    __syncthreads();                                                              \
    _Pragma("unroll 2")                                                           \
    for (int t = 0; t < (NT); t++) {                                              \
        const int cur = t & 1;                                                    \
        if (t + 1 < (NT)) { GLOAD((t + 1) * BK); }                                \
        _Pragma("unroll") for (int kk = 0; kk < BK; kk++) {                       \
            float4 a0 = *(const float4*)&As[cur][kk][ty * 8];                     \
            float4 a1 = *(const float4*)&As[cur][kk][ty * 8 + 4];                 \
            float4 b0 = *(const float4*)&Bs[cur][kk][tx * 8];                     \
            float4 b1 = *(const float4*)&Bs[cur][kk][tx * 8 + 4];                 \
            float av[8] = {a0.x,a0.y,a0.z,a0.w,a1.x,a1.y,a1.z,a1.w};              \
            float bv[8] = {b0.x,b0.y,b0.z,b0.w,b1.x,b1.y,b1.z,b1.w};              \
            _Pragma("unroll") for (int i = 0; i < 8; i++)                         \
            _Pragma("unroll") for (int j = 0; j < 8; j++)                         \
                acc[i][j] += av[i] * bv[j];                                       \
        }                                                                         \
        if (t + 1 < (NT)) {                                                       \
            const int nb = (t + 1) & 1;                                           \
            As[nb][lk+0][lr]=ra.x; As[nb][lk+1][lr]=ra.y; As[nb][lk+2][lr]=ra.z; As[nb][lk+3][lr]=ra.w; \
            Bs[nb][lk+0][lr]=rb.x; Bs[nb][lk+1][lr]=rb.y; Bs[nb][lk+2][lr]=rb.z; Bs[nb][lk+3][lr]=rb.w; \
            __syncthreads();                                                      \
        }                                                                         \
    }

#define GEMM_PROLOG                                  \
    __shared__ float As[2][BK][PITCH];               \
    __shared__ float Bs[2][BK][PITCH];               \
    const int tid = threadIdx.x;                     \
    const int tx = tid & 15, ty = tid >> 4;          \
    const int lr = tid >> 1, lk = (tid & 1) << 2;

// ================= fused projection GEMM: C = A·[Wpf|Wxf|Wpb|Wxb]^T + bias ===
__global__ void __launch_bounds__(256, 2)
gemm_proj(const float* __restrict__ A,
          const float* __restrict__ Wpf, const float* __restrict__ bpf, float* __restrict__ pxf,
          const float* __restrict__ Wxf, const float* __restrict__ bxf, float* __restrict__ x2f,
          const float* __restrict__ Wpb, const float* __restrict__ bpb, float* __restrict__ pxb,
          const float* __restrict__ Wxb, const float* __restrict__ bxb, float* __restrict__ x2b)
{
    GEMM_PROLOG
    const int rowBase = blockIdx.y * BM;
    const int cb = blockIdx.x * BN;
    const int K = IN_DIM;

    const float* B; const float* bias; float* C; int segN; int lc;
    if (cb < 512)       { B = Wpf; bias = bpf; C = pxf; segN = 512; lc = cb; }
    else if (cb < 3584) { B = Wxf; bias = bxf; C = x2f; segN = G6;  lc = cb - 512; }
    else if (cb < 4096) { B = Wpb; bias = bpb; C = pxb; segN = 512; lc = cb - 3584; }
    else                { B = Wxb; bias = bxb; C = x2b; segN = G5;  lc = cb - 4096; }

    const float* pa = A + (size_t)(rowBase + lr) * K + lk;
    const float* pb = B + (size_t)(lc + lr) * K + lk;

#define LOADP(k0) { ra = *(const float4*)(pa + (k0)); rb = *(const float4*)(pb + (k0)); }
    GEMM_MAIN(IN_DIM / BK, LOADP)
#undef LOADP

    const int colT = lc + tx * 8;
#pragma unroll
    for (int i = 0; i < 8; i++) {
        const int row = rowBase + ty * 8 + i;
        float* cr = C + (size_t)row * segN + colT;
        float v[8];
#pragma unroll
        for (int j = 0; j < 8; j++) v[j] = acc[i][j] + bias[colT + j];
        *(float4*)(cr)     = make_float4(v[0], v[1], v[2], v[3]);
        *(float4*)(cr + 4) = make_float4(v[4], v[5], v[6], v[7]);
    }
}

// ===== fw level GEMM: G[r] = h[lch]@Wl^T + h[rch]@Wr^T + x2[node] + bl + br ===
__global__ void __launch_bounds__(256, 2)
gemm_fw(const float* __restrict__ hbuf,
        const int* __restrict__ lch, const int* __restrict__ rch,
        const float* __restrict__ Wl, const float* __restrict__ Wr,
        const float* __restrict__ bl, const float* __restrict__ br,
        const float* __restrict__ x2, float* __restrict__ G,
        int s, int m)
{
    GEMM_PROLOG
    const int rowBase = blockIdx.y * BM;
    const int colBase = blockIdx.x * BN;

    int r0 = rowBase + lr; if (r0 >= m) r0 = m - 1;
    const int node = s + r0;
    const float* pa1 = hbuf + (size_t)lch[node] * H + lk;
    const float* pa2 = hbuf + (size_t)rch[node] * H + lk;
    const float* pb1 = Wl + (size_t)(colBase + lr) * H + lk;
    const float* pb2 = Wr + (size_t)(colBase + lr) * H + lk;

#define LOADF(k0) { if ((k0) < H) { ra = *(const float4*)(pa1 + (k0)); rb = *(const float4*)(pb1 + (k0)); } \
                    else { ra = *(const float4*)(pa2 + (k0) - H); rb = *(const float4*)(pb2 + (k0) - H); } }
    GEMM_MAIN((2 * H) / BK, LOADF)
#undef LOADF

    const int colT = colBase + tx * 8;
    float bv[8];
#pragma unroll
    for (int j = 0; j < 8; j++) bv[j] = bl[colT + j] + br[colT + j];
#pragma unroll
    for (int i = 0; i < 8; i++) {
        const int row = rowBase + ty * 8 + i;
        if (row < m) {
            const float* xr = x2 + (size_t)(s + row) * G6 + colT;
            float v[8];
#pragma unroll
            for (int j = 0; j < 8; j++) v[j] = acc[i][j] + bv[j] + xr[j];
            float* cr = G + (size_t)row * G6 + colT;
            *(float4*)(cr)     = make_float4(v[0], v[1], v[2], v[3]);
            *(float4*)(cr + 4) = make_float4(v[4], v[5], v[6], v[7]);
        }
    }
}

// ===== bw parent projection: Yp[s+r] = h_bw[s+r] @ Wh^T  (raw, no bias) ======
__global__ void __launch_bounds__(256, 2)
gemm_yp(const float* __restrict__ hbuf, const float* __restrict__ Wh,
        float* __restrict__ Yp, int s, int m)
{
    GEMM_PROLOG
    const int rowBase = blockIdx.y * BM;
    const int colBase = blockIdx.x * BN;

    int r0 = rowBase + lr; if (r0 >= m) r0 = m - 1;
    const float* pa = hbuf + (size_t)(s + r0) * H + lk;
    const float* pb = Wh + (size_t)(colBase + lr) * H + lk;

#define LOADY(k0) { ra = *(const float4*)(pa + (k0)); rb = *(const float4*)(pb + (k0)); }
    GEMM_MAIN(H / BK, LOADY)
#undef LOADY

    const int colT = colBase + tx * 8;
#pragma unroll
    for (int i = 0; i < 8; i++) {
        const int row = rowBase + ty * 8 + i;
        if (row < m) {
            float* cr = Yp + (size_t)(s + row) * G5 + colT;
            *(float4*)(cr)     = make_float4(acc[i][0], acc[i][1], acc[i][2], acc[i][3]);
            *(float4*)(cr + 4) = make_float4(acc[i][4], acc[i][5], acc[i][6], acc[i][7]);
        }
    }
}

// --------- forward gates (handles leaf rows with gemm_m cutoff) --------------
__global__ void gates_fw(const float* __restrict__ G, const float* __restrict__ x2,
                         const float* __restrict__ px,
                         const float* __restrict__ bl, const float* __restrict__ br,
                         float* __restrict__ cbuf, float* __restrict__ hbuf,
                         const int* __restrict__ lch, const int* __restrict__ rch,
                         int s, int gemm_m, float* __restrict__ dst) {
    const int j = blockIdx.x;
    const int col = threadIdx.x;
    const int node = s + j;
    float vi, vo, vfl, vfr, vu, vr;
    if (j < gemm_m) {
        const float* g = G + (size_t)j * G6;
        vi = g[col];         vo = g[H + col];
        vfl = g[2 * H + col]; vfr = g[3 * H + col];
        vu = g[4 * H + col]; vr = g[5 * H + col];
    } else {  // leaf: children are zero rows -> g = x2 + bl + br
        const float* g = x2 + (size_t)node * G6;
        vi  = g[col]         + bl[col]         + br[col];
        vo  = g[H + col]     + bl[H + col]     + br[H + col];
        vfl = g[2 * H + col] + bl[2 * H + col] + br[2 * H + col];
        vfr = g[3 * H + col] + bl[3 * H + col] + br[3 * H + col];
        vu  = g[4 * H + col] + bl[4 * H + col] + br[4 * H + col];
        vr  = g[5 * H + col] + bl[5 * H + col] + br[5 * H + col];
    }
    float iv = sigm(vi), ov = sigm(vo), fl = sigm(vfl), fr = sigm(vfr);
    float uv = tanhf(vu), rv = sigm(vr);
    float cl = cbuf[(size_t)lch[node] * H + col];
    float cr = cbuf[(size_t)rch[node] * H + col];
    float c = iv * uv + fl * cl + fr * cr;
    float hc = ov * tanhf(c);
    float hf = rv * hc + (1.f - rv) * px[(size_t)node * H + col];
    cbuf[(size_t)node * H + col] = c;
    hbuf[(size_t)node * H + col] = hf;
    dst[(size_t)node * IN_DIM + col] = hf;       // fused concat (fw half)
}

// --------- backward gates (reads parent projection Yp) -----------------------
__global__ void gates_bw(const float* __restrict__ Yp, const float* __restrict__ x2,
                         const float* __restrict__ px, const float* __restrict__ bh,
                         float* __restrict__ cbuf, float* __restrict__ hbuf,
                         const int* __restrict__ par,
                         int s, int useYp, float* __restrict__ dst) {
    const int j = blockIdx.x;
    const int col = threadIdx.x;
    const int node = s + j;
    const float* g = x2 + (size_t)node * G5;
    float vi = g[col]         + bh[col];
    float vo = g[H + col]     + bh[H + col];
    float vf = g[2 * H + col] + bh[2 * H + col];
    float vu = g[3 * H + col] + bh[3 * H + col];
    float vr = g[4 * H + col] + bh[4 * H + col];
    if (useYp) {
        const float* y = Yp + (size_t)par[node] * G5;
        vi += y[col]; vo += y[H + col]; vf += y[2 * H + col];
        vu += y[3 * H + col]; vr += y[4 * H + col];
    }
    float iv = sigm(vi), ov = sigm(vo), fv = sigm(vf);
    float uv = tanhf(vu), rv = sigm(vr);
    float cp = cbuf[(size_t)par[node] * H + col];
    float c = iv * uv + fv * cp;
    float hc = ov * tanhf(c);
    float hf = rv * hc + (1.f - rv) * px[(size_t)node * H + col];
    cbuf[(size_t)node * H + col] = c;
    hbuf[(size_t)node * H + col] = hf;
    dst[(size_t)node * IN_DIM + H + col] = hf;   // fused concat (bw half)
}

// ------------------------------- launch ---------------------------------------
extern "C" void kernel_launch(void* const* d_in, const int* in_sizes, int n_in,
                              void* d_out, int out_size) {
    const float* features = (const float*)d_in[0];
    const float* fw_Wp = (const float*)d_in[1];
    const float* fw_bp = (const float*)d_in[2];
    const float* fw_Wx = (const float*)d_in[3];
    const float* fw_bx = (const float*)d_in[4];
    const float* fw_Wl = (const float*)d_in[5];
    const float* fw_bl = (const float*)d_in[6];
    const float* fw_Wr = (const float*)d_in[7];
    const float* fw_br = (const float*)d_in[8];
    const float* bw_Wp = (const float*)d_in[9];
    const float* bw_bp = (const float*)d_in[10];
    const float* bw_Wx = (const float*)d_in[11];
    const float* bw_bx = (const float*)d_in[12];
    const float* bw_Wh = (const float*)d_in[13];
    const float* bw_bh = (const float*)d_in[14];
    const int* left   = (const int*)d_in[17];
    const int* right  = (const int*)d_in[18];
    const int* parent = (const int*)d_in[19];
    float* out = (float*)d_out;

    float *px_fw, *x2_fw, *px_bw, *x2_bw, *h_fw, *c_fw, *h_bw, *c_bw, *Gs, *Yp, *feat;
    cudaGetSymbolAddress((void**)&px_fw, g_px_fw);
    cudaGetSymbolAddress((void**)&x2_fw, g_x2_fw);
    cudaGetSymbolAddress((void**)&px_bw, g_px_bw);
    cudaGetSymbolAddress((void**)&x2_bw, g_x2_bw);
    cudaGetSymbolAddress((void**)&h_fw, g_h_fw);
    cudaGetSymbolAddress((void**)&c_fw, g_c_fw);
    cudaGetSymbolAddress((void**)&h_bw, g_h_bw);
    cudaGetSymbolAddress((void**)&c_bw, g_c_bw);
    cudaGetSymbolAddress((void**)&Gs, g_G);
    cudaGetSymbolAddress((void**)&Yp, g_Yp);
    cudaGetSymbolAddress((void**)&feat, g_feat);

    zero_slots_kernel<<<1, H>>>();

    static const int LSTART[NLEV] = {0, 1, 3, 7, 15, 31, 63, 127, 255, 511, 1023, 2047, 4095};
    static const int LSIZE[NLEV]  = {1, 2, 4, 8, 16, 32, 64, 128, 256, 512, 1024, 2048, 1};

    const float* cur = features;

    for (int l = 0; l < 2; l++) {
        const float* Wp_f = fw_Wp + (size_t)l * H * IN_DIM;
        const float* bp_f = fw_bp + (size_t)l * H;
        const float* Wx_f = fw_Wx + (size_t)l * G6 * IN_DIM;
        const float* bx_f = fw_bx + (size_t)l * G6;
        const float* Wl_  = fw_Wl + (size_t)l * G6 * H;
        const float* bl_  = fw_bl + (size_t)l * G6;
        const float* Wr_  = fw_Wr + (size_t)l * G6 * H;
        const float* br_  = fw_br + (size_t)l * G6;
        const float* Wp_b = bw_Wp + (size_t)l * H * IN_DIM;
        const float* bp_b = bw_bp + (size_t)l * H;
        const float* Wx_b = bw_Wx + (size_t)l * G5 * IN_DIM;
        const float* bx_b = bw_bx + (size_t)l * G5;
        const float* Wh_  = bw_Wh + (size_t)l * G5 * H;
        const float* bh_  = bw_bh + (size_t)l * G5;

        float* dst = (l == 1) ? out : feat;

        // fused input projections: one GEMM, N = 512+3072+512+2560 = 6656
        gemm_proj<<<dim3(6656 / BN, N_OBJ / BM), 256>>>(
            cur, Wp_f, bp_f, px_fw, Wx_f, bx_f, x2_fw,
                 Wp_b, bp_b, px_bw, Wx_b, bx_b, x2_bw);

        // ---------------- forward: leaves -> root -----------------------------
        for (int d = NLEV - 1; d >= 0; d--) {
            const int m = LSIZE[d], s = LSTART[d];
            // interior rows needing a child GEMM: all for d<=10, one (node 2047)
            // for d==11, none for d==12 (all-leaf level)
            const int mg = (d <= 10) ? m : ((d == 11) ? 1 : 0);
            if (mg > 0)
                gemm_fw<<<dim3(G6 / BN, (mg + BM - 1) / BM), 256>>>(
                    h_fw, left, right, Wl_, Wr_, bl_, br_, x2_fw, Gs, s, mg);
            gates_fw<<<m, H>>>(Gs, x2_fw, px_fw, bl_, br_, c_fw, h_fw,
                               left, right, s, mg, dst);
        }

        // ---------------- backward: root -> leaves ----------------------------
        for (int d = 0; d < NLEV; d++) {
            const int m = LSIZE[d], s = LSTART[d];
            gates_bw<<<m, H>>>(Yp, x2_bw, px_bw, bh_, c_bw, h_bw,
                               parent, s, (d > 0) ? 1 : 0, dst);
            // project this level's h for its children (nodes with children only)
            const int mg = (d <= 10) ? m : ((d == 11) ? 1 : 0);
            if (mg > 0)
                gemm_yp<<<dim3(G5 / BN, (mg + BM - 1) / BM), 256>>>(
                    h_bw, Wh_, Yp, s, mg);
        }

        cur = feat;
    }
}

// round 4
// speedup vs baseline: 1.9517x; 1.4845x over previous
#include <cuda_runtime.h>
#include <math.h>

#define N_OBJ  4096
#define H      512
#define IN_DIM 1024
#define G6     3072
#define G5     2560
#define NLEV   13
#define BM 128
#define BN 128
#define BK 8
#define PITCH 132

// ---------------- scratch (no allocation allowed -> device globals) ----------
__device__ float g_px_fw[N_OBJ * H];
__device__ float g_x2_fw[N_OBJ * G6];
__device__ float g_px_bw[N_OBJ * H];
__device__ float g_x2_bw[N_OBJ * G5];
__device__ float g_h_fw[(N_OBJ + 1) * H];   // slot N_OBJ = permanent zeros
__device__ float g_c_fw[(N_OBJ + 1) * H];
__device__ float g_h_bw[(N_OBJ + 1) * H];
__device__ float g_c_bw[(N_OBJ + 1) * H];
__device__ float g_G[1024 * G6];            // fw split-K partials: (z*mg+row)*G6
__device__ float g_stageA[1024 * G5];       // bw parent-proj partials (ping)
__device__ float g_stageB[1024 * G5];       // bw parent-proj partials (pong)
__device__ float g_feat[N_OBJ * IN_DIM];

__device__ __forceinline__ float sigm(float x) { return 1.0f / (1.0f + expf(-x)); }

__global__ void zero_slots_kernel() {
    int t = threadIdx.x;
    g_h_fw[N_OBJ * H + t] = 0.f;
    g_c_fw[N_OBJ * H + t] = 0.f;
    g_h_bw[N_OBJ * H + t] = 0.f;
    g_c_bw[N_OBJ * H + t] = 0.f;
}

// ---------------- FFMA2 (packed f32x2) 8x8 fragment step ---------------------
// acc[i2][j]: (row 2*i2, row 2*i2+1) packed pair, column j.
__device__ __forceinline__ void ffma2_tile(const float (*Asl)[PITCH],
                                           const float (*Bsl)[PITCH],
                                           float2 (&acc)[4][8], int ty8, int tx8) {
#pragma unroll
    for (int kk = 0; kk < BK; kk++) {
        const ulonglong2* ap = (const ulonglong2*)(Asl[kk] + ty8);
        ulonglong2 u01 = ap[0], u23 = ap[1];
        unsigned long long a2[4] = {u01.x, u01.y, u23.x, u23.y};
        float4 b0 = *(const float4*)(Bsl[kk] + tx8);
        float4 b1 = *(const float4*)(Bsl[kk] + tx8 + 4);
        float bf[8] = {b0.x, b0.y, b0.z, b0.w, b1.x, b1.y, b1.z, b1.w};
        unsigned long long bb[8];
#pragma unroll
        for (int j = 0; j < 8; j++)
            asm("mov.b64 %0, {%1, %1};" : "=l"(bb[j]) : "r"(__float_as_uint(bf[j])));
#pragma unroll
        for (int i = 0; i < 4; i++)
#pragma unroll
            for (int j = 0; j < 8; j++)
                asm("fma.rn.f32x2 %0, %1, %2, %0;"
                    : "+l"(*reinterpret_cast<unsigned long long*>(&acc[i][j]))
                    : "l"(a2[i]), "l"(bb[j]));
    }
}

#define GEMM_PROLOG                                  \
    __shared__ float As[2][BK][PITCH];               \
    __shared__ float Bs[2][BK][PITCH];               \
    const int tid = threadIdx.x;                     \
    const int tx = tid & 15, ty = tid >> 4;          \
    const int lr = tid >> 1, lk = (tid & 1) << 2;

#define STORE_SM(b)                                                               \
    As[b][lk+0][lr]=ra.x; As[b][lk+1][lr]=ra.y; As[b][lk+2][lr]=ra.z; As[b][lk+3][lr]=ra.w; \
    Bs[b][lk+0][lr]=rb.x; Bs[b][lk+1][lr]=rb.y; Bs[b][lk+2][lr]=rb.z; Bs[b][lk+3][lr]=rb.w;

#define GEMM_MAIN(NT, KBASE, GLOAD)                                               \
    float2 acc[4][8];                                                             \
    _Pragma("unroll") for (int i = 0; i < 4; i++)                                 \
    _Pragma("unroll") for (int j = 0; j < 8; j++) acc[i][j] = make_float2(0.f, 0.f); \
    float4 ra, rb;                                                                \
    GLOAD(KBASE);                                                                 \
    STORE_SM(0)                                                                   \
    __syncthreads();                                                              \
    for (int t = 0; t < (NT); t++) {                                              \
        const int cur = t & 1;                                                    \
        if (t + 1 < (NT)) { GLOAD((KBASE) + (t + 1) * BK); }                      \
        ffma2_tile(As[cur], Bs[cur], acc, ty * 8, tx * 8);                        \
        if (t + 1 < (NT)) { STORE_SM((t + 1) & 1) __syncthreads(); }              \
    }

// ================= fused projection GEMM: C = A·[Wpf|Wxf|Wpb|Wxb]^T + bias ===
__global__ void __launch_bounds__(256, 2)
gemm_proj(const float* __restrict__ A,
          const float* __restrict__ Wpf, const float* __restrict__ bpf, float* __restrict__ pxf,
          const float* __restrict__ Wxf, const float* __restrict__ bxf, float* __restrict__ x2f,
          const float* __restrict__ Wpb, const float* __restrict__ bpb, float* __restrict__ pxb,
          const float* __restrict__ Wxb, const float* __restrict__ bxb, float* __restrict__ x2b)
{
    GEMM_PROLOG
    const int rowBase = blockIdx.y * BM;
    const int cb = blockIdx.x * BN;
    const int K = IN_DIM;

    const float* B; const float* bias; float* C; int segN; int lc;
    if (cb < 512)       { B = Wpf; bias = bpf; C = pxf; segN = 512; lc = cb; }
    else if (cb < 3584) { B = Wxf; bias = bxf; C = x2f; segN = G6;  lc = cb - 512; }
    else if (cb < 4096) { B = Wpb; bias = bpb; C = pxb; segN = 512; lc = cb - 3584; }
    else                { B = Wxb; bias = bxb; C = x2b; segN = G5;  lc = cb - 4096; }

    const float* pa = A + (size_t)(rowBase + lr) * K + lk;
    const float* pb = B + (size_t)(lc + lr) * K + lk;

#define LOADP(k0) { ra = *(const float4*)(pa + (k0)); rb = *(const float4*)(pb + (k0)); }
    GEMM_MAIN(IN_DIM / BK, 0, LOADP)
#undef LOADP

    const int colT = lc + tx * 8;
#pragma unroll
    for (int i2 = 0; i2 < 4; i2++) {
#pragma unroll
        for (int s01 = 0; s01 < 2; s01++) {
            const int row = rowBase + ty * 8 + 2 * i2 + s01;
            float* cr = C + (size_t)row * segN + colT;
            float v[8];
#pragma unroll
            for (int j = 0; j < 8; j++)
                v[j] = (s01 ? acc[i2][j].y : acc[i2][j].x) + bias[colT + j];
            *(float4*)(cr)     = make_float4(v[0], v[1], v[2], v[3]);
            *(float4*)(cr + 4) = make_float4(v[4], v[5], v[6], v[7]);
        }
    }
}

// ===== fw level GEMM (split-K): raw partial = h[lch]@Wl^T + h[rch]@Wr^T ======
__global__ void __launch_bounds__(256, 2)
gemm_fw(const float* __restrict__ hbuf,
        const int* __restrict__ lch, const int* __restrict__ rch,
        const float* __restrict__ Wl, const float* __restrict__ Wr,
        float* __restrict__ Gp, int s, int mg, int ks)
{
    GEMM_PROLOG
    const int rowBase = blockIdx.y * BM;
    const int colBase = blockIdx.x * BN;
    const int z = blockIdx.z;
    const int chunk = 1024 / ks;
    const int kBase = z * chunk;

    int r0 = rowBase + lr; if (r0 >= mg) r0 = mg - 1;
    const int node = s + r0;
    const float* pa1 = hbuf + (size_t)lch[node] * H + lk;
    const float* pa2 = hbuf + (size_t)rch[node] * H + lk;
    const float* pb1 = Wl + (size_t)(colBase + lr) * H + lk;
    const float* pb2 = Wr + (size_t)(colBase + lr) * H + lk;

#define LOADF(k0) { if ((k0) < H) { ra = *(const float4*)(pa1 + (k0)); rb = *(const float4*)(pb1 + (k0)); } \
                    else { ra = *(const float4*)(pa2 + (k0) - H); rb = *(const float4*)(pb2 + (k0) - H); } }
    GEMM_MAIN(chunk / BK, kBase, LOADF)
#undef LOADF

    const int colT = colBase + tx * 8;
#pragma unroll
    for (int i2 = 0; i2 < 4; i2++) {
#pragma unroll
        for (int s01 = 0; s01 < 2; s01++) {
            const int row = rowBase + ty * 8 + 2 * i2 + s01;
            if (row < mg) {
                float* cr = Gp + (size_t)(z * mg + row) * G6 + colT;
                float v[8];
#pragma unroll
                for (int j = 0; j < 8; j++) v[j] = (s01 ? acc[i2][j].y : acc[i2][j].x);
                *(float4*)(cr)     = make_float4(v[0], v[1], v[2], v[3]);
                *(float4*)(cr + 4) = make_float4(v[4], v[5], v[6], v[7]);
            }
        }
    }
}

// ===== bw parent projection (split-K): raw partial = h_bw[s+r] @ Wh^T ========
__global__ void __launch_bounds__(256, 2)
gemm_yp(const float* __restrict__ hbuf, const float* __restrict__ Wh,
        float* __restrict__ stage, int s, int mg, int ks)
{
    GEMM_PROLOG
    const int rowBase = blockIdx.y * BM;
    const int colBase = blockIdx.x * BN;
    const int z = blockIdx.z;
    const int chunk = H / ks;
    const int kBase = z * chunk;

    int r0 = rowBase + lr; if (r0 >= mg) r0 = mg - 1;
    const float* pa = hbuf + (size_t)(s + r0) * H + lk;
    const float* pb = Wh + (size_t)(colBase + lr) * H + lk;

#define LOADY(k0) { ra = *(const float4*)(pa + (k0)); rb = *(const float4*)(pb + (k0)); }
    GEMM_MAIN(chunk / BK, kBase, LOADY)
#undef LOADY

    const int colT = colBase + tx * 8;
#pragma unroll
    for (int i2 = 0; i2 < 4; i2++) {
#pragma unroll
        for (int s01 = 0; s01 < 2; s01++) {
            const int row = rowBase + ty * 8 + 2 * i2 + s01;
            if (row < mg) {
                float* cr = stage + (size_t)(z * mg + row) * G5 + colT;
                float v[8];
#pragma unroll
                for (int j = 0; j < 8; j++) v[j] = (s01 ? acc[i2][j].y : acc[i2][j].x);
                *(float4*)(cr)     = make_float4(v[0], v[1], v[2], v[3]);
                *(float4*)(cr + 4) = make_float4(v[4], v[5], v[6], v[7]);
            }
        }
    }
}

// --------- forward gates: reduce split-K partials + x2 + biases --------------
__global__ void gates_fw(const float* __restrict__ Gp, const float* __restrict__ x2,
                         const float* __restrict__ px,
                         const float* __restrict__ bl, const float* __restrict__ br,
                         float* __restrict__ cbuf, float* __restrict__ hbuf,
                         const int* __restrict__ lch, const int* __restrict__ rch,
                         int s, int mg, int ks, float* __restrict__ dst) {
    const int j = blockIdx.x;
    const int col = threadIdx.x;
    const int node = s + j;
    float v[6];
    const float* xr = x2 + (size_t)node * G6;
#pragma unroll
    for (int g = 0; g < 6; g++) v[g] = xr[g * H + col] + bl[g * H + col] + br[g * H + col];
    if (j < mg) {
        for (int z = 0; z < ks; z++) {
            const float* gp = Gp + (size_t)(z * mg + j) * G6;
#pragma unroll
            for (int g = 0; g < 6; g++) v[g] += gp[g * H + col];
        }
    }
    float iv = sigm(v[0]), ov = sigm(v[1]), fl = sigm(v[2]), fr = sigm(v[3]);
    float uv = tanhf(v[4]), rv = sigm(v[5]);
    float cl = cbuf[(size_t)lch[node] * H + col];
    float cr = cbuf[(size_t)rch[node] * H + col];
    float c = iv * uv + fl * cl + fr * cr;
    float hc = ov * tanhf(c);
    float hf = rv * hc + (1.f - rv) * px[(size_t)node * H + col];
    cbuf[(size_t)node * H + col] = c;
    hbuf[(size_t)node * H + col] = hf;
    dst[(size_t)node * IN_DIM + col] = hf;
}

// --------- backward gates: reduce parent-level staging partials --------------
__global__ void gates_bw(const float* __restrict__ stagePrev, const float* __restrict__ x2,
                         const float* __restrict__ px, const float* __restrict__ bh,
                         float* __restrict__ cbuf, float* __restrict__ hbuf,
                         const int* __restrict__ par,
                         int s, int sPar, int mPar, int ksPar, float* __restrict__ dst) {
    const int j = blockIdx.x;
    const int col = threadIdx.x;
    const int node = s + j;
    const float* xr = x2 + (size_t)node * G5;
    float v[5];
#pragma unroll
    for (int g = 0; g < 5; g++) v[g] = xr[g * H + col] + bh[g * H + col];
    if (sPar >= 0) {
        const int rp = par[node] - sPar;
        for (int z = 0; z < ksPar; z++) {
            const float* y = stagePrev + (size_t)(z * mPar + rp) * G5;
#pragma unroll
            for (int g = 0; g < 5; g++) v[g] += y[g * H + col];
        }
    }
    float iv = sigm(v[0]), ov = sigm(v[1]), fv = sigm(v[2]);
    float uv = tanhf(v[3]), rv = sigm(v[4]);
    float cp = cbuf[(size_t)par[node] * H + col];
    float c = iv * uv + fv * cp;
    float hc = ov * tanhf(c);
    float hf = rv * hc + (1.f - rv) * px[(size_t)node * H + col];
    cbuf[(size_t)node * H + col] = c;
    hbuf[(size_t)node * H + col] = hf;
    dst[(size_t)node * IN_DIM + H + col] = hf;
}

static inline int ksel(int mg) {
    if (mg <= 128) return 8;
    if (mg <= 256) return 4;
    if (mg <= 512) return 2;
    return 1;
}

// ------------------------------- launch ---------------------------------------
extern "C" void kernel_launch(void* const* d_in, const int* in_sizes, int n_in,
                              void* d_out, int out_size) {
    const float* features = (const float*)d_in[0];
    const float* fw_Wp = (const float*)d_in[1];
    const float* fw_bp = (const float*)d_in[2];
    const float* fw_Wx = (const float*)d_in[3];
    const float* fw_bx = (const float*)d_in[4];
    const float* fw_Wl = (const float*)d_in[5];
    const float* fw_bl = (const float*)d_in[6];
    const float* fw_Wr = (const float*)d_in[7];
    const float* fw_br = (const float*)d_in[8];
    const float* bw_Wp = (const float*)d_in[9];
    const float* bw_bp = (const float*)d_in[10];
    const float* bw_Wx = (const float*)d_in[11];
    const float* bw_bx = (const float*)d_in[12];
    const float* bw_Wh = (const float*)d_in[13];
    const float* bw_bh = (const float*)d_in[14];
    const int* left   = (const int*)d_in[17];
    const int* right  = (const int*)d_in[18];
    const int* parent = (const int*)d_in[19];
    float* out = (float*)d_out;

    float *px_fw, *x2_fw, *px_bw, *x2_bw, *h_fw, *c_fw, *h_bw, *c_bw, *Gs, *stA, *stB, *feat;
    cudaGetSymbolAddress((void**)&px_fw, g_px_fw);
    cudaGetSymbolAddress((void**)&x2_fw, g_x2_fw);
    cudaGetSymbolAddress((void**)&px_bw, g_px_bw);
    cudaGetSymbolAddress((void**)&x2_bw, g_x2_bw);
    cudaGetSymbolAddress((void**)&h_fw, g_h_fw);
    cudaGetSymbolAddress((void**)&c_fw, g_c_fw);
    cudaGetSymbolAddress((void**)&h_bw, g_h_bw);
    cudaGetSymbolAddress((void**)&c_bw, g_c_bw);
    cudaGetSymbolAddress((void**)&Gs, g_G);
    cudaGetSymbolAddress((void**)&stA, g_stageA);
    cudaGetSymbolAddress((void**)&stB, g_stageB);
    cudaGetSymbolAddress((void**)&feat, g_feat);

    zero_slots_kernel<<<1, H>>>();

    static const int LSTART[NLEV] = {0, 1, 3, 7, 15, 31, 63, 127, 255, 511, 1023, 2047, 4095};
    static const int LSIZE[NLEV]  = {1, 2, 4, 8, 16, 32, 64, 128, 256, 512, 1024, 2048, 1};
    // interior (has-children) row count per level
    static const int MGV[NLEV]    = {1, 2, 4, 8, 16, 32, 64, 128, 256, 512, 1024, 1, 0};

    const float* cur = features;

    for (int l = 0; l < 2; l++) {
        const float* Wp_f = fw_Wp + (size_t)l * H * IN_DIM;
        const float* bp_f = fw_bp + (size_t)l * H;
        const float* Wx_f = fw_Wx + (size_t)l * G6 * IN_DIM;
        const float* bx_f = fw_bx + (size_t)l * G6;
        const float* Wl_  = fw_Wl + (size_t)l * G6 * H;
        const float* bl_  = fw_bl + (size_t)l * G6;
        const float* Wr_  = fw_Wr + (size_t)l * G6 * H;
        const float* br_  = fw_br + (size_t)l * G6;
        const float* Wp_b = bw_Wp + (size_t)l * H * IN_DIM;
        const float* bp_b = bw_bp + (size_t)l * H;
        const float* Wx_b = bw_Wx + (size_t)l * G5 * IN_DIM;
        const float* bx_b = bw_bx + (size_t)l * G5;
        const float* Wh_  = bw_Wh + (size_t)l * G5 * H;
        const float* bh_  = bw_bh + (size_t)l * G5;

        float* dst = (l == 1) ? out : feat;

        gemm_proj<<<dim3(6656 / BN, N_OBJ / BM), 256>>>(
            cur, Wp_f, bp_f, px_fw, Wx_f, bx_f, x2_fw,
                 Wp_b, bp_b, px_bw, Wx_b, bx_b, x2_bw);

        // ---------------- forward: leaves -> root -----------------------------
        for (int d = NLEV - 1; d >= 0; d--) {
            const int m = LSIZE[d], s = LSTART[d];
            const int mg = MGV[d];
            int ks = 1;
            if (mg > 0) {
                ks = ksel(mg);
                gemm_fw<<<dim3(G6 / BN, (mg + BM - 1) / BM, ks), 256>>>(
                    h_fw, left, right, Wl_, Wr_, Gs, s, mg, ks);
            }
            gates_fw<<<m, H>>>(Gs, x2_fw, px_fw, bl_, br_, c_fw, h_fw,
                               left, right, s, mg, ks, dst);
        }

        // ---------------- backward: root -> leaves ----------------------------
        for (int d = 0; d < NLEV; d++) {
            const int m = LSIZE[d], s = LSTART[d];
            if (d == 0) {
                gates_bw<<<m, H>>>(stA, x2_bw, px_bw, bh_, c_bw, h_bw,
                                   parent, s, -1, 1, 1, dst);
            } else {
                const int mPar = MGV[d - 1];
                const int ksPar = ksel(mPar);
                const float* stPrev = ((d - 1) & 1) ? stB : stA;
                gates_bw<<<m, H>>>(stPrev, x2_bw, px_bw, bh_, c_bw, h_bw,
                                   parent, s, LSTART[d - 1], mPar, ksPar, dst);
            }
            const int mg = MGV[d];
            if (mg > 0) {
                const int ks = ksel(mg);
                float* stCur = (d & 1) ? stB : stA;
                gemm_yp<<<dim3(G5 / BN, (mg + BM - 1) / BM, ks), 256>>>(
                    h_bw, Wh_, stCur, s, mg, ks);
            }
        }

        cur = feat;
    }
}

// round 5
// speedup vs baseline: 2.1442x; 1.0986x over previous
#include <cuda_runtime.h>
#include <math.h>

#define N_OBJ  4096
#define H      512
#define IN_DIM 1024
#define G6     3072
#define G5     2560
#define NLEV   13
#define BM 128
#define BN 128
#define BK 8
#define PITCH 132

// ---------------- scratch (no allocation allowed -> device globals) ----------
__device__ float g_px_fw[N_OBJ * H];
__device__ float g_x2_fw[N_OBJ * G6];
__device__ float g_px_bw[N_OBJ * H];
__device__ float g_x2_bw[N_OBJ * G5];
__device__ float g_h_fw[(N_OBJ + 1) * H];   // slot N_OBJ = permanent zeros
__device__ float g_c_fw[(N_OBJ + 1) * H];
__device__ float g_h_bw[(N_OBJ + 1) * H];
__device__ float g_c_bw[(N_OBJ + 1) * H];
__device__ float g_G[1024 * G6];            // fw split-K partials: (z*mg+row)*G6
__device__ float g_stage[1024 * G5];        // bw parent-proj partials (same-step use)
__device__ float g_feat[N_OBJ * IN_DIM];

__device__ __forceinline__ float sigm(float x) { return 1.0f / (1.0f + expf(-x)); }

__global__ void zero_slots_kernel() {
    int t = threadIdx.x;
    g_h_fw[N_OBJ * H + t] = 0.f;
    g_c_fw[N_OBJ * H + t] = 0.f;
    g_h_bw[N_OBJ * H + t] = 0.f;
    g_c_bw[N_OBJ * H + t] = 0.f;
}

// ---------------- FFMA2 (packed f32x2) 8x8 fragment step ---------------------
__device__ __forceinline__ void ffma2_tile(const float (*Asl)[PITCH],
                                           const float (*Bsl)[PITCH],
                                           float2 (&acc)[4][8], int ty8, int tx8) {
#pragma unroll
    for (int kk = 0; kk < BK; kk++) {
        const ulonglong2* ap = (const ulonglong2*)(Asl[kk] + ty8);
        ulonglong2 u01 = ap[0], u23 = ap[1];
        unsigned long long a2[4] = {u01.x, u01.y, u23.x, u23.y};
        float4 b0 = *(const float4*)(Bsl[kk] + tx8);
        float4 b1 = *(const float4*)(Bsl[kk] + tx8 + 4);
        float bf[8] = {b0.x, b0.y, b0.z, b0.w, b1.x, b1.y, b1.z, b1.w};
        unsigned long long bb[8];
#pragma unroll
        for (int j = 0; j < 8; j++)
            asm("mov.b64 %0, {%1, %1};" : "=l"(bb[j]) : "r"(__float_as_uint(bf[j])));
#pragma unroll
        for (int i = 0; i < 4; i++)
#pragma unroll
            for (int j = 0; j < 8; j++)
                asm("fma.rn.f32x2 %0, %1, %2, %0;"
                    : "+l"(*reinterpret_cast<unsigned long long*>(&acc[i][j]))
                    : "l"(a2[i]), "l"(bb[j]));
    }
}

#define GEMM_PROLOG                                  \
    __shared__ float As[2][BK][PITCH];               \
    __shared__ float Bs[2][BK][PITCH];               \
    const int tid = threadIdx.x;                     \
    const int tx = tid & 15, ty = tid >> 4;          \
    const int lr = tid >> 1, lk = (tid & 1) << 2;

#define STORE_SM(b)                                                               \
    As[b][lk+0][lr]=ra.x; As[b][lk+1][lr]=ra.y; As[b][lk+2][lr]=ra.z; As[b][lk+3][lr]=ra.w; \
    Bs[b][lk+0][lr]=rb.x; Bs[b][lk+1][lr]=rb.y; Bs[b][lk+2][lr]=rb.z; Bs[b][lk+3][lr]=rb.w;

#define GEMM_MAIN(NT, KBASE, GLOAD)                                               \
    float2 acc[4][8];                                                             \
    _Pragma("unroll") for (int i = 0; i < 4; i++)                                 \
    _Pragma("unroll") for (int j = 0; j < 8; j++) acc[i][j] = make_float2(0.f, 0.f); \
    float4 ra, rb;                                                                \
    GLOAD(KBASE);                                                                 \
    STORE_SM(0)                                                                   \
    __syncthreads();                                                              \
    for (int t = 0; t < (NT); t++) {                                              \
        const int cur = t & 1;                                                    \
        if (t + 1 < (NT)) { GLOAD((KBASE) + (t + 1) * BK); }                      \
        ffma2_tile(As[cur], Bs[cur], acc, ty * 8, tx * 8);                        \
        if (t + 1 < (NT)) { STORE_SM((t + 1) & 1) __syncthreads(); }              \
    }

// ================= fused projection GEMM: C = A·[Wpf|Wxf|Wpb|Wxb]^T + bias ===
__global__ void __launch_bounds__(256, 2)
gemm_proj(const float* __restrict__ A,
          const float* __restrict__ Wpf, const float* __restrict__ bpf, float* __restrict__ pxf,
          const float* __restrict__ Wxf, const float* __restrict__ bxf, float* __restrict__ x2f,
          const float* __restrict__ Wpb, const float* __restrict__ bpb, float* __restrict__ pxb,
          const float* __restrict__ Wxb, const float* __restrict__ bxb, float* __restrict__ x2b)
{
    GEMM_PROLOG
    const int rowBase = blockIdx.y * BM;
    const int cb = blockIdx.x * BN;
    const int K = IN_DIM;

    const float* B; const float* bias; float* C; int segN; int lc;
    if (cb < 512)       { B = Wpf; bias = bpf; C = pxf; segN = 512; lc = cb; }
    else if (cb < 3584) { B = Wxf; bias = bxf; C = x2f; segN = G6;  lc = cb - 512; }
    else if (cb < 4096) { B = Wpb; bias = bpb; C = pxb; segN = 512; lc = cb - 3584; }
    else                { B = Wxb; bias = bxb; C = x2b; segN = G5;  lc = cb - 4096; }

    const float* pa = A + (size_t)(rowBase + lr) * K + lk;
    const float* pb = B + (size_t)(lc + lr) * K + lk;

#define LOADP(k0) { ra = *(const float4*)(pa + (k0)); rb = *(const float4*)(pb + (k0)); }
    GEMM_MAIN(IN_DIM / BK, 0, LOADP)
#undef LOADP

    const int colT = lc + tx * 8;
#pragma unroll
    for (int i2 = 0; i2 < 4; i2++) {
#pragma unroll
        for (int s01 = 0; s01 < 2; s01++) {
            const int row = rowBase + ty * 8 + 2 * i2 + s01;
            float* cr = C + (size_t)row * segN + colT;
            float v[8];
#pragma unroll
            for (int j = 0; j < 8; j++)
                v[j] = (s01 ? acc[i2][j].y : acc[i2][j].x) + bias[colT + j];
            *(float4*)(cr)     = make_float4(v[0], v[1], v[2], v[3]);
            *(float4*)(cr + 4) = make_float4(v[4], v[5], v[6], v[7]);
        }
    }
}

// ====== MEGA level GEMM: fw tiles [0,tilesF) + bw yp tiles [tilesF, ...) =====
// fw: partial(z) of h[lch]@Wl^T + h[rch]@Wr^T  -> Gp
// bw: partial(z) of h_bw[sB+r]@Wh^T            -> stage
__global__ void __launch_bounds__(256, 2)
gemm_mega(const float* __restrict__ hf,
          const int* __restrict__ lch, const int* __restrict__ rch,
          const float* __restrict__ Wl, const float* __restrict__ Wr,
          float* __restrict__ Gp, int sF, int mgF, int ksF, int rowsF, int tilesF,
          const float* __restrict__ hb, const float* __restrict__ Wh,
          float* __restrict__ stage, int sB, int mgB, int ksB, int rowsB)
{
    GEMM_PROLOG
    int bx = blockIdx.x;
    if (bx < tilesF) {
        const int colBase = (bx % 24) * BN;
        const int rowBase = ((bx / 24) % rowsF) * BM;
        const int z = bx / (24 * rowsF);
        const int chunk = 1024 / ksF;
        const int kBase = z * chunk;

        int r0 = rowBase + lr; if (r0 >= mgF) r0 = mgF - 1;
        const int node = sF + r0;
        const float* pa1 = hf + (size_t)lch[node] * H + lk;
        const float* pa2 = hf + (size_t)rch[node] * H + lk;
        const float* pb1 = Wl + (size_t)(colBase + lr) * H + lk;
        const float* pb2 = Wr + (size_t)(colBase + lr) * H + lk;

#define LOADF(k0) { if ((k0) < H) { ra = *(const float4*)(pa1 + (k0)); rb = *(const float4*)(pb1 + (k0)); } \
                    else { ra = *(const float4*)(pa2 + (k0) - H); rb = *(const float4*)(pb2 + (k0) - H); } }
        GEMM_MAIN(chunk / BK, kBase, LOADF)
#undef LOADF

        const int colT = colBase + tx * 8;
#pragma unroll
        for (int i2 = 0; i2 < 4; i2++) {
#pragma unroll
            for (int s01 = 0; s01 < 2; s01++) {
                const int row = rowBase + ty * 8 + 2 * i2 + s01;
                if (row < mgF) {
                    float* cr = Gp + (size_t)(z * mgF + row) * G6 + colT;
                    float v[8];
#pragma unroll
                    for (int j = 0; j < 8; j++) v[j] = (s01 ? acc[i2][j].y : acc[i2][j].x);
                    *(float4*)(cr)     = make_float4(v[0], v[1], v[2], v[3]);
                    *(float4*)(cr + 4) = make_float4(v[4], v[5], v[6], v[7]);
                }
            }
        }
    } else {
        bx -= tilesF;
        const int colBase = (bx % 20) * BN;
        const int rowBase = ((bx / 20) % rowsB) * BM;
        const int z = bx / (20 * rowsB);
        const int chunk = H / ksB;
        const int kBase = z * chunk;

        int r0 = rowBase + lr; if (r0 >= mgB) r0 = mgB - 1;
        const float* pa = hb + (size_t)(sB + r0) * H + lk;
        const float* pb = Wh + (size_t)(colBase + lr) * H + lk;

#define LOADY(k0) { ra = *(const float4*)(pa + (k0)); rb = *(const float4*)(pb + (k0)); }
        GEMM_MAIN(chunk / BK, kBase, LOADY)
#undef LOADY

        const int colT = colBase + tx * 8;
#pragma unroll
        for (int i2 = 0; i2 < 4; i2++) {
#pragma unroll
            for (int s01 = 0; s01 < 2; s01++) {
                const int row = rowBase + ty * 8 + 2 * i2 + s01;
                if (row < mgB) {
                    float* cr = stage + (size_t)(z * mgB + row) * G5 + colT;
                    float v[8];
#pragma unroll
                    for (int j = 0; j < 8; j++) v[j] = (s01 ? acc[i2][j].y : acc[i2][j].x);
                    *(float4*)(cr)     = make_float4(v[0], v[1], v[2], v[3]);
                    *(float4*)(cr + 4) = make_float4(v[4], v[5], v[6], v[7]);
                }
            }
        }
    }
}

// ====== MEGA gates: blocks [0,mF) = fw level nodes, [mF, mF+mB) = bw nodes ===
__global__ void gates_mega(
    const float* __restrict__ Gp, const float* __restrict__ x2f,
    const float* __restrict__ pxf,
    const float* __restrict__ bl, const float* __restrict__ br,
    float* __restrict__ cbf, float* __restrict__ hbf,
    const int* __restrict__ lch, const int* __restrict__ rch,
    int sF, int mF, int mgF, int ksF,
    const float* __restrict__ stage, const float* __restrict__ x2b,
    const float* __restrict__ pxb, const float* __restrict__ bh,
    float* __restrict__ cbb, float* __restrict__ hbb,
    const int* __restrict__ par, int sB, int sPar, int mPar, int ksPar,
    float* __restrict__ dst)
{
    const int col = threadIdx.x;
    int j = blockIdx.x;
    if (j < mF) {
        const int node = sF + j;
        float v[6];
        const float* xr = x2f + (size_t)node * G6;
#pragma unroll
        for (int g = 0; g < 6; g++) v[g] = xr[g * H + col] + bl[g * H + col] + br[g * H + col];
        if (j < mgF) {
            for (int z = 0; z < ksF; z++) {
                const float* gp = Gp + (size_t)(z * mgF + j) * G6;
#pragma unroll
                for (int g = 0; g < 6; g++) v[g] += gp[g * H + col];
            }
        }
        float iv = sigm(v[0]), ov = sigm(v[1]), fl = sigm(v[2]), fr = sigm(v[3]);
        float uv = tanhf(v[4]), rv = sigm(v[5]);
        float cl = cbf[(size_t)lch[node] * H + col];
        float cr = cbf[(size_t)rch[node] * H + col];
        float c = iv * uv + fl * cl + fr * cr;
        float hc = ov * tanhf(c);
        float hf = rv * hc + (1.f - rv) * pxf[(size_t)node * H + col];
        cbf[(size_t)node * H + col] = c;
        hbf[(size_t)node * H + col] = hf;
        dst[(size_t)node * IN_DIM + col] = hf;
    } else {
        j -= mF;
        const int node = sB + j;
        const float* xr = x2b + (size_t)node * G5;
        float v[5];
#pragma unroll
        for (int g = 0; g < 5; g++) v[g] = xr[g * H + col] + bh[g * H + col];
        if (sPar >= 0) {
            const int rp = par[node] - sPar;
            for (int z = 0; z < ksPar; z++) {
                const float* y = stage + (size_t)(z * mPar + rp) * G5;
#pragma unroll
                for (int g = 0; g < 5; g++) v[g] += y[g * H + col];
            }
        }
        float iv = sigm(v[0]), ov = sigm(v[1]), fv = sigm(v[2]);
        float uv = tanhf(v[3]), rv = sigm(v[4]);
        float cp = cbb[(size_t)par[node] * H + col];
        float c = iv * uv + fv * cp;
        float hc = ov * tanhf(c);
        float hf = rv * hc + (1.f - rv) * pxb[(size_t)node * H + col];
        cbb[(size_t)node * H + col] = c;
        hbb[(size_t)node * H + col] = hf;
        dst[(size_t)node * IN_DIM + H + col] = hf;
    }
}

static inline int ksel(int mg) {
    if (mg <= 32)  return 16;
    if (mg <= 128) return 8;
    if (mg <= 256) return 4;
    if (mg <= 512) return 2;
    return 1;
}

// ------------------------------- launch ---------------------------------------
extern "C" void kernel_launch(void* const* d_in, const int* in_sizes, int n_in,
                              void* d_out, int out_size) {
    const float* features = (const float*)d_in[0];
    const float* fw_Wp = (const float*)d_in[1];
    const float* fw_bp = (const float*)d_in[2];
    const float* fw_Wx = (const float*)d_in[3];
    const float* fw_bx = (const float*)d_in[4];
    const float* fw_Wl = (const float*)d_in[5];
    const float* fw_bl = (const float*)d_in[6];
    const float* fw_Wr = (const float*)d_in[7];
    const float* fw_br = (const float*)d_in[8];
    const float* bw_Wp = (const float*)d_in[9];
    const float* bw_bp = (const float*)d_in[10];
    const float* bw_Wx = (const float*)d_in[11];
    const float* bw_bx = (const float*)d_in[12];
    const float* bw_Wh = (const float*)d_in[13];
    const float* bw_bh = (const float*)d_in[14];
    const int* left   = (const int*)d_in[17];
    const int* right  = (const int*)d_in[18];
    const int* parent = (const int*)d_in[19];
    float* out = (float*)d_out;

    float *px_fw, *x2_fw, *px_bw, *x2_bw, *h_fw, *c_fw, *h_bw, *c_bw, *Gs, *stg, *feat;
    cudaGetSymbolAddress((void**)&px_fw, g_px_fw);
    cudaGetSymbolAddress((void**)&x2_fw, g_x2_fw);
    cudaGetSymbolAddress((void**)&px_bw, g_px_bw);
    cudaGetSymbolAddress((void**)&x2_bw, g_x2_bw);
    cudaGetSymbolAddress((void**)&h_fw, g_h_fw);
    cudaGetSymbolAddress((void**)&c_fw, g_c_fw);
    cudaGetSymbolAddress((void**)&h_bw, g_h_bw);
    cudaGetSymbolAddress((void**)&c_bw, g_c_bw);
    cudaGetSymbolAddress((void**)&Gs, g_G);
    cudaGetSymbolAddress((void**)&stg, g_stage);
    cudaGetSymbolAddress((void**)&feat, g_feat);

    zero_slots_kernel<<<1, H>>>();

    static const int LSTART[NLEV] = {0, 1, 3, 7, 15, 31, 63, 127, 255, 511, 1023, 2047, 4095};
    static const int LSIZE[NLEV]  = {1, 2, 4, 8, 16, 32, 64, 128, 256, 512, 1024, 2048, 1};
    static const int MGV[NLEV]    = {1, 2, 4, 8, 16, 32, 64, 128, 256, 512, 1024, 1, 0};

    const float* cur = features;

    for (int l = 0; l < 2; l++) {
        const float* Wp_f = fw_Wp + (size_t)l * H * IN_DIM;
        const float* bp_f = fw_bp + (size_t)l * H;
        const float* Wx_f = fw_Wx + (size_t)l * G6 * IN_DIM;
        const float* bx_f = fw_bx + (size_t)l * G6;
        const float* Wl_  = fw_Wl + (size_t)l * G6 * H;
        const float* bl_  = fw_bl + (size_t)l * G6;
        const float* Wr_  = fw_Wr + (size_t)l * G6 * H;
        const float* br_  = fw_br + (size_t)l * G6;
        const float* Wp_b = bw_Wp + (size_t)l * H * IN_DIM;
        const float* bp_b = bw_bp + (size_t)l * H;
        const float* Wx_b = bw_Wx + (size_t)l * G5 * IN_DIM;
        const float* bx_b = bw_bx + (size_t)l * G5;
        const float* Wh_  = bw_Wh + (size_t)l * G5 * H;
        const float* bh_  = bw_bh + (size_t)l * G5;

        float* dst = (l == 1) ? out : feat;

        gemm_proj<<<dim3(6656 / BN, N_OBJ / BM), 256>>>(
            cur, Wp_f, bp_f, px_fw, Wx_f, bx_f, x2_fw,
                 Wp_b, bp_b, px_bw, Wx_b, bx_b, x2_bw);

        // -------- merged fw(leaves->root) + bw(root->leaves), 13 steps --------
        for (int t = 0; t < NLEV; t++) {
            const int dF = NLEV - 1 - t;             // fw level this step
            const int sF = LSTART[dF], mF = LSIZE[dF], mgF = MGV[dF];
            const int ksF = ksel(mgF > 0 ? mgF : 1);
            const int rowsF = (mgF + BM - 1) / BM;
            const int tilesF = (mgF > 0) ? 24 * rowsF * ksF : 0;

            const int sB = LSTART[t], mB = LSIZE[t];
            const int dY = t - 1;                    // yp of parent level
            const int mgB = (t >= 1) ? MGV[dY] : 0;
            const int ksB = ksel(mgB > 0 ? mgB : 1);
            const int rowsB = (mgB + BM - 1) / BM;
            const int tilesB = (mgB > 0) ? 20 * rowsB * ksB : 0;

            if (tilesF + tilesB > 0)
                gemm_mega<<<tilesF + tilesB, 256>>>(
                    h_fw, left, right, Wl_, Wr_, Gs, sF, (mgF > 0 ? mgF : 1), ksF,
                    (rowsF > 0 ? rowsF : 1), tilesF,
                    h_bw, Wh_, stg, LSTART[dY >= 0 ? dY : 0], (mgB > 0 ? mgB : 1),
                    ksB, (rowsB > 0 ? rowsB : 1));

            gates_mega<<<mF + mB, H>>>(
                Gs, x2_fw, px_fw, bl_, br_, c_fw, h_fw, left, right,
                sF, mF, mgF, ksF,
                stg, x2_bw, px_bw, bh_, c_bw, h_bw, parent,
                sB, (t >= 1) ? LSTART[dY] : -1, (mgB > 0 ? mgB : 1), ksB,
                dst);
        }

        cur = feat;
    }
}

// round 7
// speedup vs baseline: 2.9279x; 1.3655x over previous
#include <cuda_runtime.h>
#include <math.h>
#include <stdint.h>
#include <cuda_bf16.h>

#define N_OBJ  4096
#define H      512
#define IN_DIM 1024
#define G6     3072
#define G5     2560
#define NW     6656   // 512+3072+512+2560 concat proj width
#define NLEV   13
#define BM 128
#define BN 128
#define BK 8
#define PITCH 132
#define SPITCH 24     // bf16 elems per smem row (16 data + 8 pad -> 48B pitch)

// ---------------- scratch (no allocation allowed -> device globals) ----------
__device__ float g_px_fw[N_OBJ * H];
__device__ float g_x2_fw[N_OBJ * G6];
__device__ float g_px_bw[N_OBJ * H];
__device__ float g_x2_bw[N_OBJ * G5];
__device__ float g_h_fw[(N_OBJ + 1) * H];
__device__ float g_c_fw[(N_OBJ + 1) * H];
__device__ float g_h_bw[(N_OBJ + 1) * H];
__device__ float g_c_bw[(N_OBJ + 1) * H];
__device__ float g_G[1024 * G6];
__device__ float g_stage[1024 * G5];
__device__ float g_feat[N_OBJ * IN_DIM];
// bf16 split buffers for the tensor-core projection
__device__ __nv_bfloat16 g_Ahi[N_OBJ * IN_DIM];
__device__ __nv_bfloat16 g_Alo[N_OBJ * IN_DIM];
__device__ __nv_bfloat16 g_Whi[NW * IN_DIM];
__device__ __nv_bfloat16 g_Wlo[NW * IN_DIM];

__device__ __forceinline__ float sigm(float x) { return 1.0f / (1.0f + expf(-x)); }

__global__ void zero_slots_kernel() {
    int t = threadIdx.x;
    g_h_fw[N_OBJ * H + t] = 0.f;
    g_c_fw[N_OBJ * H + t] = 0.f;
    g_h_bw[N_OBJ * H + t] = 0.f;
    g_c_bw[N_OBJ * H + t] = 0.f;
}

// ---------------- bf16 hi/lo split (4 floats per thread) ----------------------
__global__ void split_bf16(const float* __restrict__ s, __nv_bfloat16* __restrict__ hi,
                           __nv_bfloat16* __restrict__ lo, int n4) {
    int i = blockIdx.x * blockDim.x + threadIdx.x;
    if (i < n4) {
        float4 v = ((const float4*)s)[i];
        float f[4] = {v.x, v.y, v.z, v.w};
        __nv_bfloat16 h[4], l[4];
#pragma unroll
        for (int k = 0; k < 4; k++) {
            h[k] = __float2bfloat16(f[k]);
            l[k] = __float2bfloat16(f[k] - __bfloat162float(h[k]));
        }
        unsigned int h01 = (unsigned int)*(unsigned short*)&h[0] |
                           ((unsigned int)*(unsigned short*)&h[1] << 16);
        unsigned int h23 = (unsigned int)*(unsigned short*)&h[2] |
                           ((unsigned int)*(unsigned short*)&h[3] << 16);
        unsigned int l01 = (unsigned int)*(unsigned short*)&l[0] |
                           ((unsigned int)*(unsigned short*)&l[1] << 16);
        unsigned int l23 = (unsigned int)*(unsigned short*)&l[2] |
                           ((unsigned int)*(unsigned short*)&l[3] << 16);
        ((uint2*)hi)[i] = make_uint2(h01, h23);
        ((uint2*)lo)[i] = make_uint2(l01, l23);
    }
}

#define MMA_BF16(acc, A, b0_, b1_)                                               \
    asm volatile("mma.sync.aligned.m16n8k16.row.col.f32.bf16.bf16.f32 "          \
                 "{%0,%1,%2,%3},{%4,%5,%6,%7},{%8,%9},{%0,%1,%2,%3};"            \
                 : "+f"(acc[0]), "+f"(acc[1]), "+f"(acc[2]), "+f"(acc[3])        \
                 : "r"(A[0]), "r"(A[1]), "r"(A[2]), "r"(A[3]), "r"(b0_), "r"(b1_))

// ========== tensor-core projection: C = A·Wcat^T + bias, bf16x3 split ========
// block 128x128, 8 warps (warpM = wid&3 -> 32 rows, warpN = wid>>2 -> 64 cols)
__global__ void __launch_bounds__(256, 2)
proj_tc(const float* __restrict__ bpf, float* __restrict__ pxf,
        const float* __restrict__ bxf, float* __restrict__ x2f,
        const float* __restrict__ bpb, float* __restrict__ pxb,
        const float* __restrict__ bxb, float* __restrict__ x2b)
{
    __shared__ __align__(16) __nv_bfloat16 sm[2][4][128 * SPITCH]; // Ahi,Alo,Bhi,Blo
    const int tid = threadIdx.x;
    const int wid = tid >> 5, lane = tid & 31;
    const int gid = lane >> 2, tig = lane & 3;
    const int warpM = wid & 3, warpN = wid >> 2;
    const int rowBase = blockIdx.y * BM;
    const int cb = blockIdx.x * BN;

    // segment routing (block is always fully inside one segment)
    const float* bias; float* C; int segN, lc;
    if (cb < 512)       { bias = bpf; C = pxf; segN = 512; lc = cb; }
    else if (cb < 3584) { bias = bxf; C = x2f; segN = G6;  lc = cb - 512; }
    else if (cb < 4096) { bias = bpb; C = pxb; segN = 512; lc = cb - 3584; }
    else                { bias = bxb; C = x2b; segN = G5;  lc = cb - 4096; }

    const int lrow = tid >> 1;          // loader row 0..127
    const int lhalf = (tid & 1) << 3;   // 0 or 8 (bf16 elems)
    const size_t aBase = (size_t)(rowBase + lrow) * IN_DIM + lhalf;
    const size_t bBase = (size_t)(cb + lrow) * IN_DIM + lhalf;
    const int smOff = lrow * SPITCH + lhalf;

    float acc[2][8][4];
#pragma unroll
    for (int mt = 0; mt < 2; mt++)
#pragma unroll
        for (int nt = 0; nt < 8; nt++)
#pragma unroll
            for (int q = 0; q < 4; q++) acc[mt][nt][q] = 0.f;

    uint4 rAh, rAl, rBh, rBl;
#define PROJ_LOAD(kb)                                                  \
    rAh = *(const uint4*)(g_Ahi + aBase + (kb));                       \
    rAl = *(const uint4*)(g_Alo + aBase + (kb));                       \
    rBh = *(const uint4*)(g_Whi + bBase + (kb));                       \
    rBl = *(const uint4*)(g_Wlo + bBase + (kb));
#define PROJ_STORE(b)                                                  \
    *(uint4*)&sm[b][0][smOff] = rAh;                                   \
    *(uint4*)&sm[b][1][smOff] = rAl;                                   \
    *(uint4*)&sm[b][2][smOff] = rBh;                                   \
    *(uint4*)&sm[b][3][smOff] = rBl;

    PROJ_LOAD(0)
    PROJ_STORE(0)
    __syncthreads();

    const int NSTAGE = IN_DIM / 16;
    for (int s = 0; s < NSTAGE; s++) {
        const int buf = s & 1;
        if (s + 1 < NSTAGE) { PROJ_LOAD((s + 1) * 16) }

        const __nv_bfloat16* Ah = sm[buf][0];
        const __nv_bfloat16* Al = sm[buf][1];
        const __nv_bfloat16* Bh = sm[buf][2];
        const __nv_bfloat16* Bl = sm[buf][3];

        unsigned int ah[2][4], al[2][4];
#pragma unroll
        for (int mt = 0; mt < 2; mt++) {
            const int rb = (warpM * 32 + mt * 16 + gid) * SPITCH + 2 * tig;
            ah[mt][0] = *(const unsigned int*)&Ah[rb];
            ah[mt][1] = *(const unsigned int*)&Ah[rb + 8 * SPITCH];
            ah[mt][2] = *(const unsigned int*)&Ah[rb + 8];
            ah[mt][3] = *(const unsigned int*)&Ah[rb + 8 * SPITCH + 8];
            al[mt][0] = *(const unsigned int*)&Al[rb];
            al[mt][1] = *(const unsigned int*)&Al[rb + 8 * SPITCH];
            al[mt][2] = *(const unsigned int*)&Al[rb + 8];
            al[mt][3] = *(const unsigned int*)&Al[rb + 8 * SPITCH + 8];
        }
#pragma unroll
        for (int nt = 0; nt < 8; nt++) {
            const int nb = (warpN * 64 + nt * 8 + gid) * SPITCH + 2 * tig;
            unsigned int bh0 = *(const unsigned int*)&Bh[nb];
            unsigned int bh1 = *(const unsigned int*)&Bh[nb + 8];
            unsigned int bl0 = *(const unsigned int*)&Bl[nb];
            unsigned int bl1 = *(const unsigned int*)&Bl[nb + 8];
#pragma unroll
            for (int mt = 0; mt < 2; mt++) {
                MMA_BF16(acc[mt][nt], ah[mt], bh0, bh1);
                MMA_BF16(acc[mt][nt], ah[mt], bl0, bl1);
                MMA_BF16(acc[mt][nt], al[mt], bh0, bh1);
            }
        }
        if (s + 1 < NSTAGE) {
            PROJ_STORE((s + 1) & 1)
            __syncthreads();
        }
    }

    // epilogue: C frag rows gid/gid+8, cols 2tig,2tig+1
#pragma unroll
    for (int mt = 0; mt < 2; mt++) {
#pragma unroll
        for (int nt = 0; nt < 8; nt++) {
            const int col = lc + warpN * 64 + nt * 8 + 2 * tig;
            const float b0 = bias[col], b1 = bias[col + 1];
            const int r0 = rowBase + warpM * 32 + mt * 16 + gid;
            float* c0 = C + (size_t)r0 * segN + col;
            c0[0] = acc[mt][nt][0] + b0;
            c0[1] = acc[mt][nt][1] + b1;
            float* c1 = C + (size_t)(r0 + 8) * segN + col;
            c1[0] = acc[mt][nt][2] + b0;
            c1[1] = acc[mt][nt][3] + b1;
        }
    }
}

// ---------------- FFMA2 (packed f32x2) 8x8 fragment step (level chain) -------
__device__ __forceinline__ void ffma2_tile(const float (*Asl)[PITCH],
                                           const float (*Bsl)[PITCH],
                                           float2 (&acc)[4][8], int ty8, int tx8) {
#pragma unroll
    for (int kk = 0; kk < BK; kk++) {
        const ulonglong2* ap = (const ulonglong2*)(Asl[kk] + ty8);
        ulonglong2 u01 = ap[0], u23 = ap[1];
        unsigned long long a2[4] = {u01.x, u01.y, u23.x, u23.y};
        float4 b0 = *(const float4*)(Bsl[kk] + tx8);
        float4 b1 = *(const float4*)(Bsl[kk] + tx8 + 4);
        float bf[8] = {b0.x, b0.y, b0.z, b0.w, b1.x, b1.y, b1.z, b1.w};
        unsigned long long bb[8];
#pragma unroll
        for (int j = 0; j < 8; j++)
            asm("mov.b64 %0, {%1, %1};" : "=l"(bb[j]) : "r"(__float_as_uint(bf[j])));
#pragma unroll
        for (int i = 0; i < 4; i++)
#pragma unroll
            for (int j = 0; j < 8; j++)
                asm("fma.rn.f32x2 %0, %1, %2, %0;"
                    : "+l"(*reinterpret_cast<unsigned long long*>(&acc[i][j]))
                    : "l"(a2[i]), "l"(bb[j]));
    }
}

#define GEMM_PROLOG                                  \
    __shared__ float As[2][BK][PITCH];               \
    __shared__ float Bs[2][BK][PITCH];               \
    const int tid = threadIdx.x;                     \
    const int tx = tid & 15, ty = tid >> 4;          \
    const int lr = tid >> 1, lk = (tid & 1) << 2;

#define STORE_SM(b)                                                               \
    As[b][lk+0][lr]=ra.x; As[b][lk+1][lr]=ra.y; As[b][lk+2][lr]=ra.z; As[b][lk+3][lr]=ra.w; \
    Bs[b][lk+0][lr]=rb.x; Bs[b][lk+1][lr]=rb.y; Bs[b][lk+2][lr]=rb.z; Bs[b][lk+3][lr]=rb.w;

#define GEMM_MAIN(NT, KBASE, GLOAD)                                               \
    float2 acc[4][8];                                                             \
    _Pragma("unroll") for (int i = 0; i < 4; i++)                                 \
    _Pragma("unroll") for (int j = 0; j < 8; j++) acc[i][j] = make_float2(0.f, 0.f); \
    float4 ra, rb;                                                                \
    GLOAD(KBASE);                                                                 \
    STORE_SM(0)                                                                   \
    __syncthreads();                                                              \
    for (int t = 0; t < (NT); t++) {                                              \
        const int cur = t & 1;                                                    \
        if (t + 1 < (NT)) { GLOAD((KBASE) + (t + 1) * BK); }                      \
        ffma2_tile(As[cur], Bs[cur], acc, ty * 8, tx * 8);                        \
        if (t + 1 < (NT)) { STORE_SM((t + 1) & 1) __syncthreads(); }              \
    }

// ====== MEGA level GEMM: fw tiles [0,tilesF) + bw yp tiles [tilesF, ...) =====
__global__ void __launch_bounds__(256, 2)
gemm_mega(const float* __restrict__ hf,
          const int* __restrict__ lch, const int* __restrict__ rch,
          const float* __restrict__ Wl, const float* __restrict__ Wr,
          float* __restrict__ Gp, int sF, int mgF, int ksF, int rowsF, int tilesF,
          const float* __restrict__ hb, const float* __restrict__ Wh,
          float* __restrict__ stage, int sB, int mgB, int ksB, int rowsB)
{
    GEMM_PROLOG
    int bx = blockIdx.x;
    if (bx < tilesF) {
        const int colBase = (bx % 24) * BN;
        const int rowBase = ((bx / 24) % rowsF) * BM;
        const int z = bx / (24 * rowsF);
        const int chunk = 1024 / ksF;
        const int kBase = z * chunk;

        int r0 = rowBase + lr; if (r0 >= mgF) r0 = mgF - 1;
        const int node = sF + r0;
        const float* pa1 = hf + (size_t)lch[node] * H + lk;
        const float* pa2 = hf + (size_t)rch[node] * H + lk;
        const float* pb1 = Wl + (size_t)(colBase + lr) * H + lk;
        const float* pb2 = Wr + (size_t)(colBase + lr) * H + lk;

#define LOADF(k0) { if ((k0) < H) { ra = *(const float4*)(pa1 + (k0)); rb = *(const float4*)(pb1 + (k0)); } \
                    else { ra = *(const float4*)(pa2 + (k0) - H); rb = *(const float4*)(pb2 + (k0) - H); } }
        GEMM_MAIN(chunk / BK, kBase, LOADF)
#undef LOADF

        const int colT = colBase + tx * 8;
#pragma unroll
        for (int i2 = 0; i2 < 4; i2++) {
#pragma unroll
            for (int s01 = 0; s01 < 2; s01++) {
                const int row = rowBase + ty * 8 + 2 * i2 + s01;
                if (row < mgF) {
                    float* cr = Gp + (size_t)(z * mgF + row) * G6 + colT;
                    float v[8];
#pragma unroll
                    for (int j = 0; j < 8; j++) v[j] = (s01 ? acc[i2][j].y : acc[i2][j].x);
                    *(float4*)(cr)     = make_float4(v[0], v[1], v[2], v[3]);
                    *(float4*)(cr + 4) = make_float4(v[4], v[5], v[6], v[7]);
                }
            }
        }
    } else {
        bx -= tilesF;
        const int colBase = (bx % 20) * BN;
        const int rowBase = ((bx / 20) % rowsB) * BM;
        const int z = bx / (20 * rowsB);
        const int chunk = H / ksB;
        const int kBase = z * chunk;

        int r0 = rowBase + lr; if (r0 >= mgB) r0 = mgB - 1;
        const float* pa = hb + (size_t)(sB + r0) * H + lk;
        const float* pb = Wh + (size_t)(colBase + lr) * H + lk;

#define LOADY(k0) { ra = *(const float4*)(pa + (k0)); rb = *(const float4*)(pb + (k0)); }
        GEMM_MAIN(chunk / BK, kBase, LOADY)
#undef LOADY

        const int colT = colBase + tx * 8;
#pragma unroll
        for (int i2 = 0; i2 < 4; i2++) {
#pragma unroll
            for (int s01 = 0; s01 < 2; s01++) {
                const int row = rowBase + ty * 8 + 2 * i2 + s01;
                if (row < mgB) {
                    float* cr = stage + (size_t)(z * mgB + row) * G5 + colT;
                    float v[8];
#pragma unroll
                    for (int j = 0; j < 8; j++) v[j] = (s01 ? acc[i2][j].y : acc[i2][j].x);
                    *(float4*)(cr)     = make_float4(v[0], v[1], v[2], v[3]);
                    *(float4*)(cr + 4) = make_float4(v[4], v[5], v[6], v[7]);
                }
            }
        }
    }
}

// ====== MEGA gates ============================================================
__global__ void gates_mega(
    const float* __restrict__ Gp, const float* __restrict__ x2f,
    const float* __restrict__ pxf,
    const float* __restrict__ bl, const float* __restrict__ br,
    float* __restrict__ cbf, float* __restrict__ hbf,
    const int* __restrict__ lch, const int* __restrict__ rch,
    int sF, int mF, int mgF, int ksF,
    const float* __restrict__ stage, const float* __restrict__ x2b,
    const float* __restrict__ pxb, const float* __restrict__ bh,
    float* __restrict__ cbb, float* __restrict__ hbb,
    const int* __restrict__ par, int sB, int sPar, int mPar, int ksPar,
    float* __restrict__ dst)
{
    const int col = threadIdx.x;
    int j = blockIdx.x;
    if (j < mF) {
        const int node = sF + j;
        float v[6];
        const float* xr = x2f + (size_t)node * G6;
#pragma unroll
        for (int g = 0; g < 6; g++) v[g] = xr[g * H + col] + bl[g * H + col] + br[g * H + col];
        if (j < mgF) {
            for (int z = 0; z < ksF; z++) {
                const float* gp = Gp + (size_t)(z * mgF + j) * G6;
#pragma unroll
                for (int g = 0; g < 6; g++) v[g] += gp[g * H + col];
            }
        }
        float iv = sigm(v[0]), ov = sigm(v[1]), fl = sigm(v[2]), fr = sigm(v[3]);
        float uv = tanhf(v[4]), rv = sigm(v[5]);
        float cl = cbf[(size_t)lch[node] * H + col];
        float cr = cbf[(size_t)rch[node] * H + col];
        float c = iv * uv + fl * cl + fr * cr;
        float hc = ov * tanhf(c);
        float hf = rv * hc + (1.f - rv) * pxf[(size_t)node * H + col];
        cbf[(size_t)node * H + col] = c;
        hbf[(size_t)node * H + col] = hf;
        dst[(size_t)node * IN_DIM + col] = hf;
    } else {
        j -= mF;
        const int node = sB + j;
        const float* xr = x2b + (size_t)node * G5;
        float v[5];
#pragma unroll
        for (int g = 0; g < 5; g++) v[g] = xr[g * H + col] + bh[g * H + col];
        if (sPar >= 0) {
            const int rp = par[node] - sPar;
            for (int z = 0; z < ksPar; z++) {
                const float* y = stage + (size_t)(z * mPar + rp) * G5;
#pragma unroll
                for (int g = 0; g < 5; g++) v[g] += y[g * H + col];
            }
        }
        float iv = sigm(v[0]), ov = sigm(v[1]), fv = sigm(v[2]);
        float uv = tanhf(v[3]), rv = sigm(v[4]);
        float cp = cbb[(size_t)par[node] * H + col];
        float c = iv * uv + fv * cp;
        float hc = ov * tanhf(c);
        float hf = rv * hc + (1.f - rv) * pxb[(size_t)node * H + col];
        cbb[(size_t)node * H + col] = c;
        hbb[(size_t)node * H + col] = hf;
        dst[(size_t)node * IN_DIM + H + col] = hf;
    }
}

static inline int ksel(int mg) {
    if (mg <= 32)  return 16;
    if (mg <= 128) return 8;
    if (mg <= 256) return 4;
    if (mg <= 512) return 2;
    return 1;
}

// ------------------------------- launch ---------------------------------------
extern "C" void kernel_launch(void* const* d_in, const int* in_sizes, int n_in,
                              void* d_out, int out_size) {
    const float* features = (const float*)d_in[0];
    const float* fw_Wp = (const float*)d_in[1];
    const float* fw_bp = (const float*)d_in[2];
    const float* fw_Wx = (const float*)d_in[3];
    const float* fw_bx = (const float*)d_in[4];
    const float* fw_Wl = (const float*)d_in[5];
    const float* fw_bl = (const float*)d_in[6];
    const float* fw_Wr = (const float*)d_in[7];
    const float* fw_br = (const float*)d_in[8];
    const float* bw_Wp = (const float*)d_in[9];
    const float* bw_bp = (const float*)d_in[10];
    const float* bw_Wx = (const float*)d_in[11];
    const float* bw_bx = (const float*)d_in[12];
    const float* bw_Wh = (const float*)d_in[13];
    const float* bw_bh = (const float*)d_in[14];
    const int* left   = (const int*)d_in[17];
    const int* right  = (const int*)d_in[18];
    const int* parent = (const int*)d_in[19];
    float* out = (float*)d_out;

    float *px_fw, *x2_fw, *px_bw, *x2_bw, *h_fw, *c_fw, *h_bw, *c_bw, *Gs, *stg, *feat;
    __nv_bfloat16 *Ahi, *Alo, *Whi, *Wlo;
    cudaGetSymbolAddress((void**)&px_fw, g_px_fw);
    cudaGetSymbolAddress((void**)&x2_fw, g_x2_fw);
    cudaGetSymbolAddress((void**)&px_bw, g_px_bw);
    cudaGetSymbolAddress((void**)&x2_bw, g_x2_bw);
    cudaGetSymbolAddress((void**)&h_fw, g_h_fw);
    cudaGetSymbolAddress((void**)&c_fw, g_c_fw);
    cudaGetSymbolAddress((void**)&h_bw, g_h_bw);
    cudaGetSymbolAddress((void**)&c_bw, g_c_bw);
    cudaGetSymbolAddress((void**)&Gs, g_G);
    cudaGetSymbolAddress((void**)&stg, g_stage);
    cudaGetSymbolAddress((void**)&feat, g_feat);
    cudaGetSymbolAddress((void**)&Ahi, g_Ahi);
    cudaGetSymbolAddress((void**)&Alo, g_Alo);
    cudaGetSymbolAddress((void**)&Whi, g_Whi);
    cudaGetSymbolAddress((void**)&Wlo, g_Wlo);

    zero_slots_kernel<<<1, H>>>();

    static const int LSTART[NLEV] = {0, 1, 3, 7, 15, 31, 63, 127, 255, 511, 1023, 2047, 4095};
    static const int LSIZE[NLEV]  = {1, 2, 4, 8, 16, 32, 64, 128, 256, 512, 1024, 2048, 1};
    static const int MGV[NLEV]    = {1, 2, 4, 8, 16, 32, 64, 128, 256, 512, 1024, 1, 0};

    const float* cur = features;

    for (int l = 0; l < 2; l++) {
        const float* Wp_f = fw_Wp + (size_t)l * H * IN_DIM;
        const float* bp_f = fw_bp + (size_t)l * H;
        const float* Wx_f = fw_Wx + (size_t)l * G6 * IN_DIM;
        const float* bx_f = fw_bx + (size_t)l * G6;
        const float* Wl_  = fw_Wl + (size_t)l * G6 * H;
        const float* bl_  = fw_bl + (size_t)l * G6;
        const float* Wr_  = fw_Wr + (size_t)l * G6 * H;
        const float* br_  = fw_br + (size_t)l * G6;
        const float* Wp_b = bw_Wp + (size_t)l * H * IN_DIM;
        const float* bp_b = bw_bp + (size_t)l * H;
        const float* Wx_b = bw_Wx + (size_t)l * G5 * IN_DIM;
        const float* bx_b = bw_bx + (size_t)l * G5;
        const float* Wh_  = bw_Wh + (size_t)l * G5 * H;
        const float* bh_  = bw_bh + (size_t)l * G5;

        float* dst = (l == 1) ? out : feat;

        // --- bf16 hi/lo splits: A and the concatenated weight [6656,1024] -----
        {
            int n4 = N_OBJ * IN_DIM / 4;
            split_bf16<<<(n4 + 255) / 256, 256>>>(cur, Ahi, Alo, n4);
            n4 = 512 * IN_DIM / 4;
            split_bf16<<<(n4 + 255) / 256, 256>>>(Wp_f, Whi, Wlo, n4);
            n4 = G6 * IN_DIM / 4;
            split_bf16<<<(n4 + 255) / 256, 256>>>(Wx_f, Whi + (size_t)512 * IN_DIM,
                                                  Wlo + (size_t)512 * IN_DIM, n4);
            n4 = 512 * IN_DIM / 4;
            split_bf16<<<(n4 + 255) / 256, 256>>>(Wp_b, Whi + (size_t)3584 * IN_DIM,
                                                  Wlo + (size_t)3584 * IN_DIM, n4);
            n4 = G5 * IN_DIM / 4;
            split_bf16<<<(n4 + 255) / 256, 256>>>(Wx_b, Whi + (size_t)4096 * IN_DIM,
                                                  Wlo + (size_t)4096 * IN_DIM, n4);
        }

        // --- tensor-core projection -------------------------------------------
        proj_tc<<<dim3(NW / BN, N_OBJ / BM), 256>>>(
            bp_f, px_fw, bx_f, x2_fw, bp_b, px_bw, bx_b, x2_bw);

        // -------- merged fw(leaves->root) + bw(root->leaves), 13 steps --------
        for (int t = 0; t < NLEV; t++) {
            const int dF = NLEV - 1 - t;
            const int sF = LSTART[dF], mF = LSIZE[dF], mgF = MGV[dF];
            const int ksF = ksel(mgF > 0 ? mgF : 1);
            const int rowsF = (mgF + BM - 1) / BM;
            const int tilesF = (mgF > 0) ? 24 * rowsF * ksF : 0;

            const int sB = LSTART[t], mB = LSIZE[t];
            const int dY = t - 1;
            const int mgB = (t >= 1) ? MGV[dY] : 0;
            const int ksB = ksel(mgB > 0 ? mgB : 1);
            const int rowsB = (mgB + BM - 1) / BM;
            const int tilesB = (mgB > 0) ? 20 * rowsB * ksB : 0;

            if (tilesF + tilesB > 0)
                gemm_mega<<<tilesF + tilesB, 256>>>(
                    h_fw, left, right, Wl_, Wr_, Gs, sF, (mgF > 0 ? mgF : 1), ksF,
                    (rowsF > 0 ? rowsF : 1), tilesF,
                    h_bw, Wh_, stg, LSTART[dY >= 0 ? dY : 0], (mgB > 0 ? mgB : 1),
                    ksB, (rowsB > 0 ? rowsB : 1));

            gates_mega<<<mF + mB, H>>>(
                Gs, x2_fw, px_fw, bl_, br_, c_fw, h_fw, left, right,
                sF, mF, mgF, ksF,
                stg, x2_bw, px_bw, bh_, c_bw, h_bw, parent,
                sB, (t >= 1) ? LSTART[dY] : -1, (mgB > 0 ? mgB : 1), ksB,
                dst);
        }

        cur = feat;
    }
}

// round 8
// speedup vs baseline: 3.9427x; 1.3466x over previous
#include <cuda_runtime.h>
#include <math.h>
#include <stdint.h>
#include <cuda_bf16.h>

#define N_OBJ  4096
#define H      512
#define IN_DIM 1024
#define G6     3072
#define G5     2560
#define NW     6656
#define NLEV   13
#define BM 128
#define BN 128
#define SPITCH 24     // bf16 elems per smem row (16 data + 8 pad -> 48B pitch)

// ---------------- scratch (no allocation allowed -> device globals) ----------
__device__ float g_px_fw[N_OBJ * H];
__device__ float g_x2_fw[N_OBJ * G6];
__device__ float g_px_bw[N_OBJ * H];
__device__ float g_x2_bw[N_OBJ * G5];
__device__ float g_c_fw[(N_OBJ + 1) * H];
__device__ float g_c_bw[(N_OBJ + 1) * H];
__device__ float g_G[2048 * G6];            // fw split-K partials
__device__ float g_stage[2048 * G5];        // bw parent-proj partials
__device__ float g_feat[N_OBJ * IN_DIM];
// bf16 hi/lo state + weights
__device__ __nv_bfloat16 g_hfw_hi[(N_OBJ + 1) * H];
__device__ __nv_bfloat16 g_hfw_lo[(N_OBJ + 1) * H];
__device__ __nv_bfloat16 g_hbw_hi[(N_OBJ + 1) * H];
__device__ __nv_bfloat16 g_hbw_lo[(N_OBJ + 1) * H];
__device__ __nv_bfloat16 g_Ahi[N_OBJ * IN_DIM];
__device__ __nv_bfloat16 g_Alo[N_OBJ * IN_DIM];
__device__ __nv_bfloat16 g_Whi[NW * IN_DIM];
__device__ __nv_bfloat16 g_Wlo[NW * IN_DIM];
__device__ __nv_bfloat16 g_Wfw_hi[G6 * 1024];   // [Wl | Wr] concat
__device__ __nv_bfloat16 g_Wfw_lo[G6 * 1024];
__device__ __nv_bfloat16 g_Wbw_hi[G5 * H];      // Wh
__device__ __nv_bfloat16 g_Wbw_lo[G5 * H];

__device__ __forceinline__ float sigm(float x) { return 1.0f / (1.0f + expf(-x)); }

__global__ void zero_slots_kernel() {
    int t = threadIdx.x;
    g_c_fw[N_OBJ * H + t] = 0.f;
    g_c_bw[N_OBJ * H + t] = 0.f;
    __nv_bfloat16 z = __float2bfloat16(0.f);
    g_hfw_hi[N_OBJ * H + t] = z; g_hfw_lo[N_OBJ * H + t] = z;
    g_hbw_hi[N_OBJ * H + t] = z; g_hbw_lo[N_OBJ * H + t] = z;
}

// ---------------- bf16 hi/lo split helpers ------------------------------------
__device__ __forceinline__ void split4(float4 v, unsigned int& h01, unsigned int& h23,
                                       unsigned int& l01, unsigned int& l23) {
    float f[4] = {v.x, v.y, v.z, v.w};
    __nv_bfloat16 h[4], l[4];
#pragma unroll
    for (int k = 0; k < 4; k++) {
        h[k] = __float2bfloat16(f[k]);
        l[k] = __float2bfloat16(f[k] - __bfloat162float(h[k]));
    }
    h01 = (unsigned int)*(unsigned short*)&h[0] | ((unsigned int)*(unsigned short*)&h[1] << 16);
    h23 = (unsigned int)*(unsigned short*)&h[2] | ((unsigned int)*(unsigned short*)&h[3] << 16);
    l01 = (unsigned int)*(unsigned short*)&l[0] | ((unsigned int)*(unsigned short*)&l[1] << 16);
    l23 = (unsigned int)*(unsigned short*)&l[2] | ((unsigned int)*(unsigned short*)&l[3] << 16);
}

__global__ void split_bf16(const float* __restrict__ s, __nv_bfloat16* __restrict__ hi,
                           __nv_bfloat16* __restrict__ lo, int n4) {
    int i = blockIdx.x * blockDim.x + threadIdx.x;
    if (i < n4) {
        unsigned int h01, h23, l01, l23;
        split4(((const float4*)s)[i], h01, h23, l01, l23);
        ((uint2*)hi)[i] = make_uint2(h01, h23);
        ((uint2*)lo)[i] = make_uint2(l01, l23);
    }
}

// split src[rows x 512] into dst with row pitch 1024 at column offset dstOff
__global__ void split_bf16_pad(const float* __restrict__ s, __nv_bfloat16* __restrict__ hi,
                               __nv_bfloat16* __restrict__ lo, int rows, int dstOff) {
    int i = blockIdx.x * blockDim.x + threadIdx.x;   // float4 units
    if (i < rows * 128) {
        int row = i >> 7, c4 = i & 127;
        unsigned int h01, h23, l01, l23;
        split4(((const float4*)s)[i], h01, h23, l01, l23);
        size_t d = (size_t)row * 256 + (dstOff >> 2) + c4;  // uint2 units, pitch 1024
        ((uint2*)hi)[d] = make_uint2(h01, h23);
        ((uint2*)lo)[d] = make_uint2(l01, l23);
    }
}

#define MMA_BF16(acc, A, b0_, b1_)                                               \
    asm volatile("mma.sync.aligned.m16n8k16.row.col.f32.bf16.bf16.f32 "          \
                 "{%0,%1,%2,%3},{%4,%5,%6,%7},{%8,%9},{%0,%1,%2,%3};"            \
                 : "+f"(acc[0]), "+f"(acc[1]), "+f"(acc[2]), "+f"(acc[3])        \
                 : "r"(A[0]), "r"(A[1]), "r"(A[2]), "r"(A[3]), "r"(b0_), "r"(b1_))

// shared MMA mainloop body (needs sm, warp ids, loader macros in scope)
#define TC_COMPUTE(buf)                                                          \
    {                                                                            \
        const __nv_bfloat16* Ah = sm[buf][0];                                    \
        const __nv_bfloat16* Al = sm[buf][1];                                    \
        const __nv_bfloat16* Bh = sm[buf][2];                                    \
        const __nv_bfloat16* Bl = sm[buf][3];                                    \
        unsigned int ah[2][4], al[2][4];                                         \
        _Pragma("unroll") for (int mt = 0; mt < 2; mt++) {                       \
            const int rb = (warpM * 32 + mt * 16 + gid) * SPITCH + 2 * tig;      \
            ah[mt][0] = *(const unsigned int*)&Ah[rb];                           \
            ah[mt][1] = *(const unsigned int*)&Ah[rb + 8 * SPITCH];              \
            ah[mt][2] = *(const unsigned int*)&Ah[rb + 8];                       \
            ah[mt][3] = *(const unsigned int*)&Ah[rb + 8 * SPITCH + 8];          \
            al[mt][0] = *(const unsigned int*)&Al[rb];                           \
            al[mt][1] = *(const unsigned int*)&Al[rb + 8 * SPITCH];              \
            al[mt][2] = *(const unsigned int*)&Al[rb + 8];                       \
            al[mt][3] = *(const unsigned int*)&Al[rb + 8 * SPITCH + 8];          \
        }                                                                        \
        _Pragma("unroll") for (int nt = 0; nt < 8; nt++) {                       \
            const int nb = (warpN * 64 + nt * 8 + gid) * SPITCH + 2 * tig;       \
            unsigned int bh0 = *(const unsigned int*)&Bh[nb];                    \
            unsigned int bh1 = *(const unsigned int*)&Bh[nb + 8];                \
            unsigned int bl0 = *(const unsigned int*)&Bl[nb];                    \
            unsigned int bl1 = *(const unsigned int*)&Bl[nb + 8];                \
            _Pragma("unroll") for (int mt = 0; mt < 2; mt++) {                   \
                MMA_BF16(acc[mt][nt], ah[mt], bh0, bh1);                         \
                MMA_BF16(acc[mt][nt], ah[mt], bl0, bl1);                         \
                MMA_BF16(acc[mt][nt], al[mt], bh0, bh1);                         \
            }                                                                    \
        }                                                                        \
    }

// ========== tensor-core projection: C = A·Wcat^T + bias ======================
__global__ void __launch_bounds__(256, 2)
proj_tc(const float* __restrict__ bpf, float* __restrict__ pxf,
        const float* __restrict__ bxf, float* __restrict__ x2f,
        const float* __restrict__ bpb, float* __restrict__ pxb,
        const float* __restrict__ bxb, float* __restrict__ x2b)
{
    __shared__ __align__(16) __nv_bfloat16 sm[2][4][128 * SPITCH];
    const int tid = threadIdx.x;
    const int wid = tid >> 5, lane = tid & 31;
    const int gid = lane >> 2, tig = lane & 3;
    const int warpM = wid & 3, warpN = wid >> 2;
    const int rowBase = blockIdx.y * BM;
    const int cb = blockIdx.x * BN;

    const float* bias; float* C; int segN, lc;
    if (cb < 512)       { bias = bpf; C = pxf; segN = 512; lc = cb; }
    else if (cb < 3584) { bias = bxf; C = x2f; segN = G6;  lc = cb - 512; }
    else if (cb < 4096) { bias = bpb; C = pxb; segN = 512; lc = cb - 3584; }
    else                { bias = bxb; C = x2b; segN = G5;  lc = cb - 4096; }

    const int lrow = tid >> 1;
    const int lhalf = (tid & 1) << 3;
    const size_t aBase = (size_t)(rowBase + lrow) * IN_DIM + lhalf;
    const size_t bBase = (size_t)(cb + lrow) * IN_DIM + lhalf;
    const int smOff = lrow * SPITCH + lhalf;

    float acc[2][8][4];
#pragma unroll
    for (int mt = 0; mt < 2; mt++)
#pragma unroll
        for (int nt = 0; nt < 8; nt++)
#pragma unroll
            for (int q = 0; q < 4; q++) acc[mt][nt][q] = 0.f;

    uint4 rAh, rAl, rBh, rBl;
#define PROJ_LOAD(kb)                                                  \
    rAh = *(const uint4*)(g_Ahi + aBase + (kb));                       \
    rAl = *(const uint4*)(g_Alo + aBase + (kb));                       \
    rBh = *(const uint4*)(g_Whi + bBase + (kb));                       \
    rBl = *(const uint4*)(g_Wlo + bBase + (kb));
#define SM_STORE(b)                                                    \
    *(uint4*)&sm[b][0][smOff] = rAh;                                   \
    *(uint4*)&sm[b][1][smOff] = rAl;                                   \
    *(uint4*)&sm[b][2][smOff] = rBh;                                   \
    *(uint4*)&sm[b][3][smOff] = rBl;

    PROJ_LOAD(0)
    SM_STORE(0)
    __syncthreads();

    const int NSTAGE = IN_DIM / 16;
    for (int s = 0; s < NSTAGE; s++) {
        const int buf = s & 1;
        if (s + 1 < NSTAGE) { PROJ_LOAD((s + 1) * 16) }
        TC_COMPUTE(buf)
        if (s + 1 < NSTAGE) {
            SM_STORE((s + 1) & 1)
            __syncthreads();
        }
    }
#undef PROJ_LOAD

#pragma unroll
    for (int mt = 0; mt < 2; mt++) {
#pragma unroll
        for (int nt = 0; nt < 8; nt++) {
            const int col = lc + warpN * 64 + nt * 8 + 2 * tig;
            const float b0 = bias[col], b1 = bias[col + 1];
            const int r0 = rowBase + warpM * 32 + mt * 16 + gid;
            float* c0 = C + (size_t)r0 * segN + col;
            c0[0] = acc[mt][nt][0] + b0;
            c0[1] = acc[mt][nt][1] + b1;
            float* c1 = C + (size_t)(r0 + 8) * segN + col;
            c1[0] = acc[mt][nt][2] + b0;
            c1[1] = acc[mt][nt][3] + b1;
        }
    }
}

// ====== MEGA level GEMM (tensor core): fw tiles then bw tiles ================
// fw: partial(z) of [h_lch | h_rch] @ [Wl|Wr]^T -> Gp   (K=1024)
// bw: partial(z) of h_bw[sB+r] @ Wh^T           -> stage (K=512)
__global__ void __launch_bounds__(256, 2)
mega_tc(const int* __restrict__ lch, const int* __restrict__ rch,
        float* __restrict__ Gp, int sF, int mgF, int ksF, int rowsF, int tilesF,
        float* __restrict__ stage, int sB, int mgB, int ksB, int rowsB)
{
    __shared__ __align__(16) __nv_bfloat16 sm[2][4][128 * SPITCH];
    const int tid = threadIdx.x;
    const int wid = tid >> 5, lane = tid & 31;
    const int gid = lane >> 2, tig = lane & 3;
    const int warpM = wid & 3, warpN = wid >> 2;
    const int lrow = tid >> 1, lhalf = (tid & 1) << 3;
    const int smOff = lrow * SPITCH + lhalf;

    int bx = blockIdx.x;
    const bool isF = bx < tilesF;
    if (!isF) bx -= tilesF;
    const int colTiles = isF ? 24 : 20;
    const int rows = isF ? rowsF : rowsB;
    const int colBase = (bx % colTiles) * BN;
    const int rowBase = ((bx / colTiles) % rows) * BM;
    const int z = bx / (colTiles * rows);
    const int mg = isF ? mgF : mgB;
    const int KTOT = isF ? 1024 : 512;
    const int ks = isF ? ksF : ksB;
    const int chunk = KTOT / ks;
    const int kBase = z * chunk;

    int r0 = rowBase + lrow; if (r0 >= mg) r0 = mg - 1;
    const __nv_bfloat16 *paHi0, *paLo0, *paHi1, *paLo1;
    if (isF) {
        const int node = sF + r0;
        const int il = lch[node], ir = rch[node];
        paHi0 = g_hfw_hi + (size_t)il * H;
        paLo0 = g_hfw_lo + (size_t)il * H;
        paHi1 = g_hfw_hi + (size_t)ir * H - H;   // indexed with k in [512,1024)
        paLo1 = g_hfw_lo + (size_t)ir * H - H;
    } else {
        const int node = sB + r0;
        paHi0 = g_hbw_hi + (size_t)node * H;
        paLo0 = g_hbw_lo + (size_t)node * H;
        paHi1 = paHi0; paLo1 = paLo0;
    }
    const __nv_bfloat16* pbHi = (isF ? g_Wfw_hi : g_Wbw_hi) + (size_t)(colBase + lrow) * KTOT;
    const __nv_bfloat16* pbLo = (isF ? g_Wfw_lo : g_Wbw_lo) + (size_t)(colBase + lrow) * KTOT;

    float acc[2][8][4];
#pragma unroll
    for (int mt = 0; mt < 2; mt++)
#pragma unroll
        for (int nt = 0; nt < 8; nt++)
#pragma unroll
            for (int q = 0; q < 4; q++) acc[mt][nt][q] = 0.f;

    uint4 rAh, rAl, rBh, rBl;
#define MEGA_LOAD(kb) {                                                \
    const int k = (kb) + lhalf;                                        \
    const __nv_bfloat16* ph = (k < H) ? paHi0 : paHi1;                 \
    const __nv_bfloat16* pl = (k < H) ? paLo0 : paLo1;                 \
    rAh = *(const uint4*)(ph + k);                                     \
    rAl = *(const uint4*)(pl + k);                                     \
    rBh = *(const uint4*)(pbHi + k);                                   \
    rBl = *(const uint4*)(pbLo + k); }

    MEGA_LOAD(kBase)
    SM_STORE(0)
    __syncthreads();

    const int NSTAGE = chunk / 16;
    for (int s = 0; s < NSTAGE; s++) {
        const int buf = s & 1;
        if (s + 1 < NSTAGE) { MEGA_LOAD(kBase + (s + 1) * 16) }
        TC_COMPUTE(buf)
        if (s + 1 < NSTAGE) {
            SM_STORE((s + 1) & 1)
            __syncthreads();
        }
    }
#undef MEGA_LOAD

    float* outp = isF ? Gp : stage;
    const int stride = isF ? G6 : G5;
#pragma unroll
    for (int mt = 0; mt < 2; mt++) {
#pragma unroll
        for (int nt = 0; nt < 8; nt++) {
            const int col = colBase + warpN * 64 + nt * 8 + 2 * tig;
            const int ro = rowBase + warpM * 32 + mt * 16 + gid;
            if (ro < mg) {
                float* p = outp + (size_t)(z * mg + ro) * stride + col;
                p[0] = acc[mt][nt][0]; p[1] = acc[mt][nt][1];
            }
            if (ro + 8 < mg) {
                float* p = outp + (size_t)(z * mg + ro + 8) * stride + col;
                p[0] = acc[mt][nt][2]; p[1] = acc[mt][nt][3];
            }
        }
    }
}

// ====== MEGA gates ============================================================
__global__ void gates_mega(
    const float* __restrict__ Gp, const float* __restrict__ x2f,
    const float* __restrict__ pxf,
    const float* __restrict__ bl, const float* __restrict__ br,
    float* __restrict__ cbf,
    const int* __restrict__ lch, const int* __restrict__ rch,
    int sF, int mF, int mgF, int ksF,
    const float* __restrict__ stage, const float* __restrict__ x2b,
    const float* __restrict__ pxb, const float* __restrict__ bh,
    float* __restrict__ cbb,
    const int* __restrict__ par, int sB, int sPar, int mPar, int ksPar,
    float* __restrict__ dst)
{
    const int col = threadIdx.x;
    int j = blockIdx.x;
    if (j < mF) {
        const int node = sF + j;
        float v[6];
        const float* xr = x2f + (size_t)node * G6;
#pragma unroll
        for (int g = 0; g < 6; g++) v[g] = xr[g * H + col] + bl[g * H + col] + br[g * H + col];
        if (j < mgF) {
            for (int z = 0; z < ksF; z++) {
                const float* gp = Gp + (size_t)(z * mgF + j) * G6;
#pragma unroll
                for (int g = 0; g < 6; g++) v[g] += gp[g * H + col];
            }
        }
        float iv = sigm(v[0]), ov = sigm(v[1]), fl = sigm(v[2]), fr = sigm(v[3]);
        float uv = tanhf(v[4]), rv = sigm(v[5]);
        float cl = cbf[(size_t)lch[node] * H + col];
        float cr = cbf[(size_t)rch[node] * H + col];
        float c = iv * uv + fl * cl + fr * cr;
        float hc = ov * tanhf(c);
        float hf = rv * hc + (1.f - rv) * pxf[(size_t)node * H + col];
        cbf[(size_t)node * H + col] = c;
        __nv_bfloat16 hh = __float2bfloat16(hf);
        g_hfw_hi[(size_t)node * H + col] = hh;
        g_hfw_lo[(size_t)node * H + col] = __float2bfloat16(hf - __bfloat162float(hh));
        dst[(size_t)node * IN_DIM + col] = hf;
    } else {
        j -= mF;
        const int node = sB + j;
        const float* xr = x2b + (size_t)node * G5;
        float v[5];
#pragma unroll
        for (int g = 0; g < 5; g++) v[g] = xr[g * H + col] + bh[g * H + col];
        if (sPar >= 0) {
            const int rp = par[node] - sPar;
            for (int z = 0; z < ksPar; z++) {
                const float* y = stage + (size_t)(z * mPar + rp) * G5;
#pragma unroll
                for (int g = 0; g < 5; g++) v[g] += y[g * H + col];
            }
        }
        float iv = sigm(v[0]), ov = sigm(v[1]), fv = sigm(v[2]);
        float uv = tanhf(v[3]), rv = sigm(v[4]);
        float cp = cbb[(size_t)par[node] * H + col];
        float c = iv * uv + fv * cp;
        float hc = ov * tanhf(c);
        float hf = rv * hc + (1.f - rv) * pxb[(size_t)node * H + col];
        cbb[(size_t)node * H + col] = c;
        __nv_bfloat16 hh = __float2bfloat16(hf);
        g_hbw_hi[(size_t)node * H + col] = hh;
        g_hbw_lo[(size_t)node * H + col] = __float2bfloat16(hf - __bfloat162float(hh));
        dst[(size_t)node * IN_DIM + H + col] = hf;
    }
}

static inline int ksel(int mg) {
    if (mg <= 32)  return 16;
    if (mg <= 128) return 8;
    if (mg <= 512) return 4;
    return 2;
}

// ------------------------------- launch ---------------------------------------
extern "C" void kernel_launch(void* const* d_in, const int* in_sizes, int n_in,
                              void* d_out, int out_size) {
    const float* features = (const float*)d_in[0];
    const float* fw_Wp = (const float*)d_in[1];
    const float* fw_bp = (const float*)d_in[2];
    const float* fw_Wx = (const float*)d_in[3];
    const float* fw_bx = (const float*)d_in[4];
    const float* fw_Wl = (const float*)d_in[5];
    const float* fw_bl = (const float*)d_in[6];
    const float* fw_Wr = (const float*)d_in[7];
    const float* fw_br = (const float*)d_in[8];
    const float* bw_Wp = (const float*)d_in[9];
    const float* bw_bp = (const float*)d_in[10];
    const float* bw_Wx = (const float*)d_in[11];
    const float* bw_bx = (const float*)d_in[12];
    const float* bw_Wh = (const float*)d_in[13];
    const float* bw_bh = (const float*)d_in[14];
    const int* left   = (const int*)d_in[17];
    const int* right  = (const int*)d_in[18];
    const int* parent = (const int*)d_in[19];
    float* out = (float*)d_out;

    float *px_fw, *x2_fw, *px_bw, *x2_bw, *c_fw, *c_bw, *Gs, *stg, *feat;
    __nv_bfloat16 *Ahi, *Alo, *Whi, *Wlo, *Wfh, *Wfl, *Wbh, *Wbl;
    cudaGetSymbolAddress((void**)&px_fw, g_px_fw);
    cudaGetSymbolAddress((void**)&x2_fw, g_x2_fw);
    cudaGetSymbolAddress((void**)&px_bw, g_px_bw);
    cudaGetSymbolAddress((void**)&x2_bw, g_x2_bw);
    cudaGetSymbolAddress((void**)&c_fw, g_c_fw);
    cudaGetSymbolAddress((void**)&c_bw, g_c_bw);
    cudaGetSymbolAddress((void**)&Gs, g_G);
    cudaGetSymbolAddress((void**)&stg, g_stage);
    cudaGetSymbolAddress((void**)&feat, g_feat);
    cudaGetSymbolAddress((void**)&Ahi, g_Ahi);
    cudaGetSymbolAddress((void**)&Alo, g_Alo);
    cudaGetSymbolAddress((void**)&Whi, g_Whi);
    cudaGetSymbolAddress((void**)&Wlo, g_Wlo);
    cudaGetSymbolAddress((void**)&Wfh, g_Wfw_hi);
    cudaGetSymbolAddress((void**)&Wfl, g_Wfw_lo);
    cudaGetSymbolAddress((void**)&Wbh, g_Wbw_hi);
    cudaGetSymbolAddress((void**)&Wbl, g_Wbw_lo);

    zero_slots_kernel<<<1, H>>>();

    static const int LSTART[NLEV] = {0, 1, 3, 7, 15, 31, 63, 127, 255, 511, 1023, 2047, 4095};
    static const int LSIZE[NLEV]  = {1, 2, 4, 8, 16, 32, 64, 128, 256, 512, 1024, 2048, 1};
    static const int MGV[NLEV]    = {1, 2, 4, 8, 16, 32, 64, 128, 256, 512, 1024, 1, 0};

    const float* cur = features;

    for (int l = 0; l < 2; l++) {
        const float* Wp_f = fw_Wp + (size_t)l * H * IN_DIM;
        const float* bp_f = fw_bp + (size_t)l * H;
        const float* Wx_f = fw_Wx + (size_t)l * G6 * IN_DIM;
        const float* bx_f = fw_bx + (size_t)l * G6;
        const float* Wl_  = fw_Wl + (size_t)l * G6 * H;
        const float* bl_  = fw_bl + (size_t)l * G6;
        const float* Wr_  = fw_Wr + (size_t)l * G6 * H;
        const float* br_  = fw_br + (size_t)l * G6;
        const float* Wp_b = bw_Wp + (size_t)l * H * IN_DIM;
        const float* bp_b = bw_bp + (size_t)l * H;
        const float* Wx_b = bw_Wx + (size_t)l * G5 * IN_DIM;
        const float* bx_b = bw_bx + (size_t)l * G5;
        const float* Wh_  = bw_Wh + (size_t)l * G5 * H;
        const float* bh_  = bw_bh + (size_t)l * G5;

        float* dst = (l == 1) ? out : feat;

        // --- bf16 hi/lo splits ------------------------------------------------
        {
            int n4 = N_OBJ * IN_DIM / 4;
            split_bf16<<<(n4 + 255) / 256, 256>>>(cur, Ahi, Alo, n4);
            n4 = 512 * IN_DIM / 4;
            split_bf16<<<(n4 + 255) / 256, 256>>>(Wp_f, Whi, Wlo, n4);
            n4 = G6 * IN_DIM / 4;
            split_bf16<<<(n4 + 255) / 256, 256>>>(Wx_f, Whi + (size_t)512 * IN_DIM,
                                                  Wlo + (size_t)512 * IN_DIM, n4);
            n4 = 512 * IN_DIM / 4;
            split_bf16<<<(n4 + 255) / 256, 256>>>(Wp_b, Whi + (size_t)3584 * IN_DIM,
                                                  Wlo + (size_t)3584 * IN_DIM, n4);
            n4 = G5 * IN_DIM / 4;
            split_bf16<<<(n4 + 255) / 256, 256>>>(Wx_b, Whi + (size_t)4096 * IN_DIM,
                                                  Wlo + (size_t)4096 * IN_DIM, n4);
            // level weights: [Wl | Wr] concat (pitch 1024) + Wh (contiguous)
            int nf = G6 * 128;
            split_bf16_pad<<<(nf + 255) / 256, 256>>>(Wl_, Wfh, Wfl, G6, 0);
            split_bf16_pad<<<(nf + 255) / 256, 256>>>(Wr_, Wfh, Wfl, G6, 512);
            n4 = G5 * H / 4;
            split_bf16<<<(n4 + 255) / 256, 256>>>(Wh_, Wbh, Wbl, n4);
        }

        // --- tensor-core projection --------------------------------------------
        proj_tc<<<dim3(NW / BN, N_OBJ / BM), 256>>>(
            bp_f, px_fw, bx_f, x2_fw, bp_b, px_bw, bx_b, x2_bw);

        // -------- merged fw(leaves->root) + bw(root->leaves), 13 steps ---------
        for (int t = 0; t < NLEV; t++) {
            const int dF = NLEV - 1 - t;
            const int sF = LSTART[dF], mF = LSIZE[dF], mgF = MGV[dF];
            const int ksF = ksel(mgF > 0 ? mgF : 1);
            const int rowsF = (mgF + BM - 1) / BM;
            const int tilesF = (mgF > 0) ? 24 * rowsF * ksF : 0;

            const int sB = LSTART[t], mB = LSIZE[t];
            const int dY = t - 1;
            const int mgB = (t >= 1) ? MGV[dY] : 0;
            const int ksB = ksel(mgB > 0 ? mgB : 1);
            const int rowsB = (mgB + BM - 1) / BM;
            const int tilesB = (mgB > 0) ? 20 * rowsB * ksB : 0;

            if (tilesF + tilesB > 0)
                mega_tc<<<tilesF + tilesB, 256>>>(
                    left, right, Gs, sF, (mgF > 0 ? mgF : 1), ksF,
                    (rowsF > 0 ? rowsF : 1), tilesF,
                    stg, LSTART[dY >= 0 ? dY : 0], (mgB > 0 ? mgB : 1),
                    ksB, (rowsB > 0 ? rowsB : 1));

            gates_mega<<<mF + mB, H>>>(
                Gs, x2_fw, px_fw, bl_, br_, c_fw, left, right,
                sF, mF, mgF, ksF,
                stg, x2_bw, px_bw, bh_, c_bw, parent,
                sB, (t >= 1) ? LSTART[dY] : -1, (mgB > 0 ? mgB : 1), ksB,
                dst);
        }

        cur = feat;
    }
}

// round 9
// speedup vs baseline: 4.3818x; 1.1114x over previous
#include <cuda_runtime.h>
#include <math.h>
#include <stdint.h>
#include <cuda_bf16.h>

#define N_OBJ  4096
#define H      512
#define IN_DIM 1024
#define G6     3072
#define G5     2560
#define NW     6656
#define NLEV   13
#define BM 128
#define BN 128
#define SPITCH 24     // bf16 elems per smem row (16 data + 8 pad -> 48B pitch)

// ---------------- scratch (no allocation allowed -> device globals) ----------
__device__ float g_px_fw[N_OBJ * H];
__device__ float g_x2_fw[N_OBJ * G6];
__device__ float g_px_bw[N_OBJ * H];
__device__ float g_x2_bw[N_OBJ * G5];
__device__ float g_c_fw[(N_OBJ + 1) * H];
__device__ float g_c_bw[(N_OBJ + 1) * H];
__device__ float g_G[2048 * G6];
__device__ float g_stage[2048 * G5];
__device__ float g_feat[N_OBJ * IN_DIM];
__device__ __nv_bfloat16 g_hfw_hi[(N_OBJ + 1) * H];
__device__ __nv_bfloat16 g_hfw_lo[(N_OBJ + 1) * H];
__device__ __nv_bfloat16 g_hbw_hi[(N_OBJ + 1) * H];
__device__ __nv_bfloat16 g_hbw_lo[(N_OBJ + 1) * H];
__device__ __nv_bfloat16 g_Ahi[N_OBJ * IN_DIM];
__device__ __nv_bfloat16 g_Alo[N_OBJ * IN_DIM];
__device__ __nv_bfloat16 g_Whi[NW * IN_DIM];
__device__ __nv_bfloat16 g_Wlo[NW * IN_DIM];
__device__ __nv_bfloat16 g_Wfw_hi[G6 * 1024];
__device__ __nv_bfloat16 g_Wfw_lo[G6 * 1024];
__device__ __nv_bfloat16 g_Wbw_hi[G5 * H];
__device__ __nv_bfloat16 g_Wbw_lo[G5 * H];

__device__ __forceinline__ float sigm(float x) { return 1.0f / (1.0f + expf(-x)); }

__global__ void zero_slots_kernel() {
    int t = threadIdx.x;
    g_c_fw[N_OBJ * H + t] = 0.f;
    g_c_bw[N_OBJ * H + t] = 0.f;
    __nv_bfloat16 z = __float2bfloat16(0.f);
    g_hfw_hi[N_OBJ * H + t] = z; g_hfw_lo[N_OBJ * H + t] = z;
    g_hbw_hi[N_OBJ * H + t] = z; g_hbw_lo[N_OBJ * H + t] = z;
}

// ---------------- bf16 hi/lo split helpers ------------------------------------
__device__ __forceinline__ void split4(float4 v, unsigned int& h01, unsigned int& h23,
                                       unsigned int& l01, unsigned int& l23) {
    float f[4] = {v.x, v.y, v.z, v.w};
    __nv_bfloat16 h[4], l[4];
#pragma unroll
    for (int k = 0; k < 4; k++) {
        h[k] = __float2bfloat16(f[k]);
        l[k] = __float2bfloat16(f[k] - __bfloat162float(h[k]));
    }
    h01 = (unsigned int)*(unsigned short*)&h[0] | ((unsigned int)*(unsigned short*)&h[1] << 16);
    h23 = (unsigned int)*(unsigned short*)&h[2] | ((unsigned int)*(unsigned short*)&h[3] << 16);
    l01 = (unsigned int)*(unsigned short*)&l[0] | ((unsigned int)*(unsigned short*)&l[1] << 16);
    l23 = (unsigned int)*(unsigned short*)&l[2] | ((unsigned int)*(unsigned short*)&l[3] << 16);
}

// ---- one fused split kernel per layer: segments laid out in float4 space ----
// [0,S0) A ; [S0,S1) Wpf ; [S1,S2) Wxf ; [S2,S3) Wpb ; [S3,S4) Wxb ;
// [S4,S5) Wl(pad) ; [S5,S6) Wr(pad) ; [S6,S7) Wh
#define SS0 1048576
#define SS1 1179648
#define SS2 1966080
#define SS3 2097152
#define SS4 2752512
#define SS5 3145728
#define SS6 3538944
#define SS7 3866624
__global__ void split_all(const float* __restrict__ A,
                          const float* __restrict__ Wpf, const float* __restrict__ Wxf,
                          const float* __restrict__ Wpb, const float* __restrict__ Wxb,
                          const float* __restrict__ Wl, const float* __restrict__ Wr,
                          const float* __restrict__ Wh) {
    long i = (long)blockIdx.x * blockDim.x + threadIdx.x;
    if (i >= SS7) return;
    unsigned int h01, h23, l01, l23;
    if (i < SS0) {
        split4(((const float4*)A)[i], h01, h23, l01, l23);
        ((uint2*)g_Ahi)[i] = make_uint2(h01, h23);
        ((uint2*)g_Alo)[i] = make_uint2(l01, l23);
    } else if (i < SS4) {
        const float* src; long j; long doff;
        if (i < SS1)      { src = Wpf; j = i - SS0; doff = 0; }
        else if (i < SS2) { src = Wxf; j = i - SS1; doff = 131072; }
        else if (i < SS3) { src = Wpb; j = i - SS2; doff = 917504; }   // 3584*1024/4
        else              { src = Wxb; j = i - SS3; doff = 1048576; }  // 4096*1024/4
        split4(((const float4*)src)[j], h01, h23, l01, l23);
        ((uint2*)g_Whi)[doff + j] = make_uint2(h01, h23);
        ((uint2*)g_Wlo)[doff + j] = make_uint2(l01, l23);
    } else if (i < SS6) {
        const float* src; long j; long coff;
        if (i < SS5) { src = Wl; j = i - SS4; coff = 0; }
        else         { src = Wr; j = i - SS5; coff = 128; }   // +512 elems = +128 uint2
        split4(((const float4*)src)[j], h01, h23, l01, l23);
        long row = j >> 7, c4 = j & 127;
        long d = row * 256 + coff + c4;                        // pitch 1024 elems
        ((uint2*)g_Wfw_hi)[d] = make_uint2(h01, h23);
        ((uint2*)g_Wfw_lo)[d] = make_uint2(l01, l23);
    } else {
        long j = i - SS6;
        split4(((const float4*)Wh)[j], h01, h23, l01, l23);
        ((uint2*)g_Wbw_hi)[j] = make_uint2(h01, h23);
        ((uint2*)g_Wbw_lo)[j] = make_uint2(l01, l23);
    }
}

#define MMA_BF16(acc, A, b0_, b1_)                                               \
    asm volatile("mma.sync.aligned.m16n8k16.row.col.f32.bf16.bf16.f32 "          \
                 "{%0,%1,%2,%3},{%4,%5,%6,%7},{%8,%9},{%0,%1,%2,%3};"            \
                 : "+f"(acc[0]), "+f"(acc[1]), "+f"(acc[2]), "+f"(acc[3])        \
                 : "r"(A[0]), "r"(A[1]), "r"(A[2]), "r"(A[3]), "r"(b0_), "r"(b1_))

#define LDSM4(r, addr)                                                           \
    asm volatile("ldmatrix.sync.aligned.m8n8.x4.shared.b16 {%0,%1,%2,%3}, [%4];" \
                 : "=r"((r)[0]), "=r"((r)[1]), "=r"((r)[2]), "=r"((r)[3])        \
                 : "r"(addr))

#define PLANE_B  (128 * SPITCH * 2)      // bytes per plane = 6144
#define BUF_B    (4 * PLANE_B)           // bytes per stage buffer

// LDSM-based compute step: needs smem_u32, aoffA, aoffB, warpM/N, acc in scope
#define TC_COMPUTE_LDSM(buf)                                                     \
    {                                                                            \
        const unsigned int b0a = smem_u32 + (buf) * BUF_B;                       \
        unsigned int ah[2][4], al[2][4];                                         \
        LDSM4(ah[0], b0a + aoffA);                                               \
        LDSM4(ah[1], b0a + aoffA + 768);                                         \
        LDSM4(al[0], b0a + PLANE_B + aoffA);                                     \
        LDSM4(al[1], b0a + PLANE_B + aoffA + 768);                               \
        _Pragma("unroll") for (int p = 0; p < 4; p++) {                          \
            unsigned int bh[4], bl[4];                                           \
            LDSM4(bh, b0a + 2 * PLANE_B + aoffB + p * 768);                      \
            LDSM4(bl, b0a + 3 * PLANE_B + aoffB + p * 768);                      \
            _Pragma("unroll") for (int mt = 0; mt < 2; mt++) {                   \
                MMA_BF16(acc[mt][2 * p],     ah[mt], bh[0], bh[1]);              \
                MMA_BF16(acc[mt][2 * p],     ah[mt], bl[0], bl[1]);              \
                MMA_BF16(acc[mt][2 * p],     al[mt], bh[0], bh[1]);              \
                MMA_BF16(acc[mt][2 * p + 1], ah[mt], bh[2], bh[3]);              \
                MMA_BF16(acc[mt][2 * p + 1], ah[mt], bl[2], bl[3]);              \
                MMA_BF16(acc[mt][2 * p + 1], al[mt], bh[2], bh[3]);              \
            }                                                                    \
        }                                                                        \
    }

#define TC_PROLOG                                                                \
    const int tid = threadIdx.x;                                                 \
    const int wid = tid >> 5, lane = tid & 31;                                   \
    const int gid = lane >> 2, tig = lane & 3;                                   \
    const int warpM = wid & 3, warpN = wid >> 2;                                 \
    const unsigned int smem_u32 = (unsigned int)__cvta_generic_to_shared(&sm[0][0][0]); \
    const unsigned int aoffA = ((warpM * 32 + (lane & 7) + ((lane >> 3) & 1) * 8) * SPITCH \
                                + (lane >> 4) * 8) * 2;                          \
    const unsigned int aoffB = ((warpN * 64 + (lane & 7) + (lane >> 4) * 8) * SPITCH \
                                + ((lane >> 3) & 1) * 8) * 2;

// ========== tensor-core projection: C = A·Wcat^T + bias ======================
__global__ void __launch_bounds__(256, 2)
proj_tc(const float* __restrict__ bpf, float* __restrict__ pxf,
        const float* __restrict__ bxf, float* __restrict__ x2f,
        const float* __restrict__ bpb, float* __restrict__ pxb,
        const float* __restrict__ bxb, float* __restrict__ x2b)
{
    __shared__ __align__(16) __nv_bfloat16 sm[2][4][128 * SPITCH];
    TC_PROLOG
    const int rowBase = blockIdx.y * BM;
    const int cb = blockIdx.x * BN;

    const float* bias; float* C; int segN, lc;
    if (cb < 512)       { bias = bpf; C = pxf; segN = 512; lc = cb; }
    else if (cb < 3584) { bias = bxf; C = x2f; segN = G6;  lc = cb - 512; }
    else if (cb < 4096) { bias = bpb; C = pxb; segN = 512; lc = cb - 3584; }
    else                { bias = bxb; C = x2b; segN = G5;  lc = cb - 4096; }

    const int lrow = tid >> 1;
    const int lhalf = (tid & 1) << 3;
    const size_t aBase = (size_t)(rowBase + lrow) * IN_DIM + lhalf;
    const size_t bBase = (size_t)(cb + lrow) * IN_DIM + lhalf;
    const int smOff = lrow * SPITCH + lhalf;

    float acc[2][8][4];
#pragma unroll
    for (int mt = 0; mt < 2; mt++)
#pragma unroll
        for (int nt = 0; nt < 8; nt++)
#pragma unroll
            for (int q = 0; q < 4; q++) acc[mt][nt][q] = 0.f;

    uint4 rAh, rAl, rBh, rBl;
#define PROJ_LOAD(kb)                                                  \
    rAh = *(const uint4*)(g_Ahi + aBase + (kb));                       \
    rAl = *(const uint4*)(g_Alo + aBase + (kb));                       \
    rBh = *(const uint4*)(g_Whi + bBase + (kb));                       \
    rBl = *(const uint4*)(g_Wlo + bBase + (kb));
#define SM_STORE(b)                                                    \
    *(uint4*)&sm[b][0][smOff] = rAh;                                   \
    *(uint4*)&sm[b][1][smOff] = rAl;                                   \
    *(uint4*)&sm[b][2][smOff] = rBh;                                   \
    *(uint4*)&sm[b][3][smOff] = rBl;

    PROJ_LOAD(0)
    SM_STORE(0)
    __syncthreads();

    const int NSTAGE = IN_DIM / 16;
    for (int s = 0; s < NSTAGE; s++) {
        const int buf = s & 1;
        if (s + 1 < NSTAGE) { PROJ_LOAD((s + 1) * 16) }
        TC_COMPUTE_LDSM(buf)
        if (s + 1 < NSTAGE) {
            SM_STORE((s + 1) & 1)
            __syncthreads();
        }
    }
#undef PROJ_LOAD

#pragma unroll
    for (int mt = 0; mt < 2; mt++) {
#pragma unroll
        for (int nt = 0; nt < 8; nt++) {
            const int col = lc + warpN * 64 + nt * 8 + 2 * tig;
            const float b0 = bias[col], b1 = bias[col + 1];
            const int r0 = rowBase + warpM * 32 + mt * 16 + gid;
            float* c0 = C + (size_t)r0 * segN + col;
            c0[0] = acc[mt][nt][0] + b0;
            c0[1] = acc[mt][nt][1] + b1;
            float* c1 = C + (size_t)(r0 + 8) * segN + col;
            c1[0] = acc[mt][nt][2] + b0;
            c1[1] = acc[mt][nt][3] + b1;
        }
    }
}

// ====== MEGA level GEMM (tensor core): fw tiles then bw tiles ================
__global__ void __launch_bounds__(256, 2)
mega_tc(const int* __restrict__ lch, const int* __restrict__ rch,
        float* __restrict__ Gp, int sF, int mgF, int ksF, int rowsF, int tilesF,
        float* __restrict__ stage, int sB, int mgB, int ksB, int rowsB)
{
    __shared__ __align__(16) __nv_bfloat16 sm[2][4][128 * SPITCH];
    TC_PROLOG
    const int lrow = tid >> 1, lhalf = (tid & 1) << 3;
    const int smOff = lrow * SPITCH + lhalf;

    int bx = blockIdx.x;
    const bool isF = bx < tilesF;
    if (!isF) bx -= tilesF;
    const int colTiles = isF ? 24 : 20;
    const int rows = isF ? rowsF : rowsB;
    const int colBase = (bx % colTiles) * BN;
    const int rowBase = ((bx / colTiles) % rows) * BM;
    const int z = bx / (colTiles * rows);
    const int mg = isF ? mgF : mgB;
    const int KTOT = isF ? 1024 : 512;
    const int ks = isF ? ksF : ksB;
    const int chunk = KTOT / ks;
    const int kBase = z * chunk;

    int r0 = rowBase + lrow; if (r0 >= mg) r0 = mg - 1;
    const __nv_bfloat16 *paHi0, *paLo0, *paHi1, *paLo1;
    if (isF) {
        const int node = sF + r0;
        const int il = lch[node], ir = rch[node];
        paHi0 = g_hfw_hi + (size_t)il * H;
        paLo0 = g_hfw_lo + (size_t)il * H;
        paHi1 = g_hfw_hi + (size_t)ir * H - H;
        paLo1 = g_hfw_lo + (size_t)ir * H - H;
    } else {
        const int node = sB + r0;
        paHi0 = g_hbw_hi + (size_t)node * H;
        paLo0 = g_hbw_lo + (size_t)node * H;
        paHi1 = paHi0; paLo1 = paLo0;
    }
    const __nv_bfloat16* pbHi = (isF ? g_Wfw_hi : g_Wbw_hi) + (size_t)(colBase + lrow) * KTOT;
    const __nv_bfloat16* pbLo = (isF ? g_Wfw_lo : g_Wbw_lo) + (size_t)(colBase + lrow) * KTOT;

    float acc[2][8][4];
#pragma unroll
    for (int mt = 0; mt < 2; mt++)
#pragma unroll
        for (int nt = 0; nt < 8; nt++)
#pragma unroll
            for (int q = 0; q < 4; q++) acc[mt][nt][q] = 0.f;

    uint4 rAh, rAl, rBh, rBl;
#define MEGA_LOAD(kb) {                                                \
    const int k = (kb) + lhalf;                                        \
    const __nv_bfloat16* ph = (k < H) ? paHi0 : paHi1;                 \
    const __nv_bfloat16* pl = (k < H) ? paLo0 : paLo1;                 \
    rAh = *(const uint4*)(ph + k);                                     \
    rAl = *(const uint4*)(pl + k);                                     \
    rBh = *(const uint4*)(pbHi + k);                                   \
    rBl = *(const uint4*)(pbLo + k); }

    MEGA_LOAD(kBase)
    SM_STORE(0)
    __syncthreads();

    const int NSTAGE = chunk / 16;
    for (int s = 0; s < NSTAGE; s++) {
        const int buf = s & 1;
        if (s + 1 < NSTAGE) { MEGA_LOAD(kBase + (s + 1) * 16) }
        TC_COMPUTE_LDSM(buf)
        if (s + 1 < NSTAGE) {
            SM_STORE((s + 1) & 1)
            __syncthreads();
        }
    }
#undef MEGA_LOAD

    float* outp = isF ? Gp : stage;
    const int stride = isF ? G6 : G5;
#pragma unroll
    for (int mt = 0; mt < 2; mt++) {
#pragma unroll
        for (int nt = 0; nt < 8; nt++) {
            const int col = colBase + warpN * 64 + nt * 8 + 2 * tig;
            const int ro = rowBase + warpM * 32 + mt * 16 + gid;
            if (ro < mg) {
                float* p = outp + (size_t)(z * mg + ro) * stride + col;
                p[0] = acc[mt][nt][0]; p[1] = acc[mt][nt][1];
            }
            if (ro + 8 < mg) {
                float* p = outp + (size_t)(z * mg + ro + 8) * stride + col;
                p[0] = acc[mt][nt][2]; p[1] = acc[mt][nt][3];
            }
        }
    }
}

// ====== MEGA gates ============================================================
__global__ void gates_mega(
    const float* __restrict__ Gp, const float* __restrict__ x2f,
    const float* __restrict__ pxf,
    const float* __restrict__ bl, const float* __restrict__ br,
    float* __restrict__ cbf,
    const int* __restrict__ lch, const int* __restrict__ rch,
    int sF, int mF, int mgF, int ksF,
    const float* __restrict__ stage, const float* __restrict__ x2b,
    const float* __restrict__ pxb, const float* __restrict__ bh,
    float* __restrict__ cbb,
    const int* __restrict__ par, int sB, int sPar, int mPar, int ksPar,
    float* __restrict__ dst)
{
    const int col = threadIdx.x;
    int j = blockIdx.x;
    if (j < mF) {
        const int node = sF + j;
        float v[6];
        const float* xr = x2f + (size_t)node * G6;
#pragma unroll
        for (int g = 0; g < 6; g++) v[g] = xr[g * H + col] + bl[g * H + col] + br[g * H + col];
        if (j < mgF) {
            for (int z = 0; z < ksF; z++) {
                const float* gp = Gp + (size_t)(z * mgF + j) * G6;
#pragma unroll
                for (int g = 0; g < 6; g++) v[g] += gp[g * H + col];
            }
        }
        float iv = sigm(v[0]), ov = sigm(v[1]), fl = sigm(v[2]), fr = sigm(v[3]);
        float uv = tanhf(v[4]), rv = sigm(v[5]);
        float cl = cbf[(size_t)lch[node] * H + col];
        float cr = cbf[(size_t)rch[node] * H + col];
        float c = iv * uv + fl * cl + fr * cr;
        float hc = ov * tanhf(c);
        float hf = rv * hc + (1.f - rv) * pxf[(size_t)node * H + col];
        cbf[(size_t)node * H + col] = c;
        __nv_bfloat16 hh = __float2bfloat16(hf);
        g_hfw_hi[(size_t)node * H + col] = hh;
        g_hfw_lo[(size_t)node * H + col] = __float2bfloat16(hf - __bfloat162float(hh));
        dst[(size_t)node * IN_DIM + col] = hf;
    } else {
        j -= mF;
        const int node = sB + j;
        const float* xr = x2b + (size_t)node * G5;
        float v[5];
#pragma unroll
        for (int g = 0; g < 5; g++) v[g] = xr[g * H + col] + bh[g * H + col];
        if (sPar >= 0) {
            const int rp = par[node] - sPar;
            for (int z = 0; z < ksPar; z++) {
                const float* y = stage + (size_t)(z * mPar + rp) * G5;
#pragma unroll
                for (int g = 0; g < 5; g++) v[g] += y[g * H + col];
            }
        }
        float iv = sigm(v[0]), ov = sigm(v[1]), fv = sigm(v[2]);
        float uv = tanhf(v[3]), rv = sigm(v[4]);
        float cp = cbb[(size_t)par[node] * H + col];
        float c = iv * uv + fv * cp;
        float hc = ov * tanhf(c);
        float hf = rv * hc + (1.f - rv) * pxb[(size_t)node * H + col];
        cbb[(size_t)node * H + col] = c;
        __nv_bfloat16 hh = __float2bfloat16(hf);
        g_hbw_hi[(size_t)node * H + col] = hh;
        g_hbw_lo[(size_t)node * H + col] = __float2bfloat16(hf - __bfloat162float(hh));
        dst[(size_t)node * IN_DIM + H + col] = hf;
    }
}

static inline int ksel(int mg) {
    if (mg <= 32)  return 16;
    if (mg <= 128) return 8;
    if (mg <= 512) return 4;
    return 2;
}

// ------------------------------- launch ---------------------------------------
extern "C" void kernel_launch(void* const* d_in, const int* in_sizes, int n_in,
                              void* d_out, int out_size) {
    const float* features = (const float*)d_in[0];
    const float* fw_Wp = (const float*)d_in[1];
    const float* fw_bp = (const float*)d_in[2];
    const float* fw_Wx = (const float*)d_in[3];
    const float* fw_bx = (const float*)d_in[4];
    const float* fw_Wl = (const float*)d_in[5];
    const float* fw_bl = (const float*)d_in[6];
    const float* fw_Wr = (const float*)d_in[7];
    const float* fw_br = (const float*)d_in[8];
    const float* bw_Wp = (const float*)d_in[9];
    const float* bw_bp = (const float*)d_in[10];
    const float* bw_Wx = (const float*)d_in[11];
    const float* bw_bx = (const float*)d_in[12];
    const float* bw_Wh = (const float*)d_in[13];
    const float* bw_bh = (const float*)d_in[14];
    const int* left   = (const int*)d_in[17];
    const int* right  = (const int*)d_in[18];
    const int* parent = (const int*)d_in[19];
    float* out = (float*)d_out;

    float *px_fw, *x2_fw, *px_bw, *x2_bw, *c_fw, *c_bw, *Gs, *stg, *feat;
    cudaGetSymbolAddress((void**)&px_fw, g_px_fw);
    cudaGetSymbolAddress((void**)&x2_fw, g_x2_fw);
    cudaGetSymbolAddress((void**)&px_bw, g_px_bw);
    cudaGetSymbolAddress((void**)&x2_bw, g_x2_bw);
    cudaGetSymbolAddress((void**)&c_fw, g_c_fw);
    cudaGetSymbolAddress((void**)&c_bw, g_c_bw);
    cudaGetSymbolAddress((void**)&Gs, g_G);
    cudaGetSymbolAddress((void**)&stg, g_stage);
    cudaGetSymbolAddress((void**)&feat, g_feat);

    zero_slots_kernel<<<1, H>>>();

    static const int LSTART[NLEV] = {0, 1, 3, 7, 15, 31, 63, 127, 255, 511, 1023, 2047, 4095};
    static const int LSIZE[NLEV]  = {1, 2, 4, 8, 16, 32, 64, 128, 256, 512, 1024, 2048, 1};
    static const int MGV[NLEV]    = {1, 2, 4, 8, 16, 32, 64, 128, 256, 512, 1024, 1, 0};

    const float* cur = features;

    for (int l = 0; l < 2; l++) {
        const float* Wp_f = fw_Wp + (size_t)l * H * IN_DIM;
        const float* bp_f = fw_bp + (size_t)l * H;
        const float* Wx_f = fw_Wx + (size_t)l * G6 * IN_DIM;
        const float* bx_f = fw_bx + (size_t)l * G6;
        const float* Wl_  = fw_Wl + (size_t)l * G6 * H;
        const float* bl_  = fw_bl + (size_t)l * G6;
        const float* Wr_  = fw_Wr + (size_t)l * G6 * H;
        const float* br_  = fw_br + (size_t)l * G6;
        const float* Wp_b = bw_Wp + (size_t)l * H * IN_DIM;
        const float* bp_b = bw_bp + (size_t)l * H;
        const float* Wx_b = bw_Wx + (size_t)l * G5 * IN_DIM;
        const float* bx_b = bw_bx + (size_t)l * G5;
        const float* Wh_  = bw_Wh + (size_t)l * G5 * H;
        const float* bh_  = bw_bh + (size_t)l * G5;

        float* dst = (l == 1) ? out : feat;

        // one fused bf16 hi/lo split for everything this layer needs
        split_all<<<(SS7 + 255) / 256, 256>>>(cur, Wp_f, Wx_f, Wp_b, Wx_b,
                                              Wl_, Wr_, Wh_);

        proj_tc<<<dim3(NW / BN, N_OBJ / BM), 256>>>(
            bp_f, px_fw, bx_f, x2_fw, bp_b, px_bw, bx_b, x2_bw);

        for (int t = 0; t < NLEV; t++) {
            const int dF = NLEV - 1 - t;
            const int sF = LSTART[dF], mF = LSIZE[dF], mgF = MGV[dF];
            const int ksF = ksel(mgF > 0 ? mgF : 1);
            const int rowsF = (mgF + BM - 1) / BM;
            const int tilesF = (mgF > 0) ? 24 * rowsF * ksF : 0;

            const int sB = LSTART[t], mB = LSIZE[t];
            const int dY = t - 1;
            const int mgB = (t >= 1) ? MGV[dY] : 0;
            const int ksB = ksel(mgB > 0 ? mgB : 1);
            const int rowsB = (mgB + BM - 1) / BM;
            const int tilesB = (mgB > 0) ? 20 * rowsB * ksB : 0;

            if (tilesF + tilesB > 0)
                mega_tc<<<tilesF + tilesB, 256>>>(
                    left, right, Gs, sF, (mgF > 0 ? mgF : 1), ksF,
                    (rowsF > 0 ? rowsF : 1), tilesF,
                    stg, LSTART[dY >= 0 ? dY : 0], (mgB > 0 ? mgB : 1),
                    ksB, (rowsB > 0 ? rowsB : 1));

            gates_mega<<<mF + mB, H>>>(
                Gs, x2_fw, px_fw, bl_, br_, c_fw, left, right,
                sF, mF, mgF, ksF,
                stg, x2_bw, px_bw, bh_, c_bw, parent,
                sB, (t >= 1) ? LSTART[dY] : -1, (mgB > 0 ? mgB : 1), ksB,
                dst);
        }

        cur = feat;
    }
}